// round 2
// baseline (speedup 1.0000x reference)
#include <cuda_runtime.h>
#include <math.h>

#define NNODES 100000
#define NEDGES 1600000
#define INC 128
#define HID 128
#define OUTC 18

// ---------------- scratch (static device globals; no allocation) ----------------
__device__ __align__(16) float g_deg[NNODES];
__device__ __align__(16) float g_dinv[NNODES];
__device__ __align__(16) float g_h1[(size_t)NNODES * HID];     // x @ W1
__device__ __align__(16) float g_agg1[(size_t)NNODES * HID];   // aggregated layer-1
__device__ __align__(16) float g_h2[(size_t)NNODES * OUTC];    // relu(agg1) @ W2
__device__ __align__(16) float g_agg2[(size_t)NNODES * OUTC];  // aggregated layer-2
__device__ int g_src[NEDGES];
__device__ int g_dst[NEDGES];
__device__ int g_is64;

// ---------------- K_dt: detect whether edge buffer is int64 or int32 ----------------
// If int64: every odd 32-bit word (high half) is 0 since indices < 2^17.
// If int32: odd words are real indices; P(128 consecutive being all 0) ~ 0.
__global__ void k_detect(const unsigned int* __restrict__ eiw) {
    if (threadIdx.x == 0 && blockIdx.x == 0) {
        int all0 = 1;
        for (int i = 0; i < 128; i++)
            if (eiw[2 * i + 1] != 0u) { all0 = 0; break; }
        g_is64 = all0;
    }
}

// ---------------- K_cv: normalize edges to int32 src/dst ----------------
__global__ void k_convert(const void* __restrict__ ei) {
    int e = blockIdx.x * blockDim.x + threadIdx.x;
    if (e >= NEDGES) return;
    if (g_is64) {
        const long long* p = (const long long*)ei;
        g_src[e] = (int)p[e];
        g_dst[e] = (int)p[NEDGES + e];
    } else {
        const int* p = (const int*)ei;
        g_src[e] = p[e];
        g_dst[e] = p[NEDGES + e];
    }
}

// ---------------- K0: deg = 1 (self loop) ----------------
__global__ void k_init_deg() {
    int i = blockIdx.x * blockDim.x + threadIdx.x;
    if (i < NNODES) g_deg[i] = 1.0f;
}

// ---------------- K1: degree count over dst ----------------
__global__ void k_degree() {
    int e = blockIdx.x * blockDim.x + threadIdx.x;
    if (e < NEDGES) atomicAdd(&g_deg[g_dst[e]], 1.0f);
}

// ---------------- K2: dinv = rsqrt(deg) ----------------
__global__ void k_dinv() {
    int i = blockIdx.x * blockDim.x + threadIdx.x;
    if (i < NNODES) g_dinv[i] = rsqrtf(g_deg[i]);
}

// ---------------- K3: GEMM1  h1 = x @ W1 ; agg1 = b1 + dinv^2 * h1 ----------------
__global__ __launch_bounds__(256) void k_gemm1(const float* __restrict__ x,
                                               const float* __restrict__ W1,
                                               const float* __restrict__ b1) {
    __shared__ float Ws[64 * 128];   // 32 KB
    __shared__ float Xs[32 * 64];    // 8 KB
    const int row0 = blockIdx.x * 32;
    const int tid = threadIdx.x;
    const int tx = tid & 31;
    const int ty = tid >> 5;

    float acc[4][4];
#pragma unroll
    for (int r = 0; r < 4; r++)
#pragma unroll
        for (int c = 0; c < 4; c++) acc[r][c] = 0.0f;

    for (int kp = 0; kp < 2; kp++) {
        for (int i = tid; i < 64 * 128 / 4; i += 256)
            ((float4*)Ws)[i] = ((const float4*)(W1 + kp * 64 * 128))[i];
        for (int i = tid; i < 32 * 64 / 4; i += 256) {
            int r = i >> 4;
            int c4 = i & 15;
            int grow = row0 + r;
            float4 v = make_float4(0.f, 0.f, 0.f, 0.f);
            if (grow < NNODES)
                v = *(const float4*)(x + (size_t)grow * INC + kp * 64 + c4 * 4);
            ((float4*)Xs)[i] = v;
        }
        __syncthreads();
#pragma unroll 4
        for (int k = 0; k < 64; k++) {
            float wv[4], xv[4];
#pragma unroll
            for (int c = 0; c < 4; c++) wv[c] = Ws[k * 128 + tx + 32 * c];
#pragma unroll
            for (int r = 0; r < 4; r++) xv[r] = Xs[(4 * ty + r) * 64 + k];
#pragma unroll
            for (int r = 0; r < 4; r++)
#pragma unroll
                for (int c = 0; c < 4; c++) acc[r][c] = fmaf(xv[r], wv[c], acc[r][c]);
        }
        __syncthreads();
    }

#pragma unroll
    for (int r = 0; r < 4; r++) {
        int grow = row0 + 4 * ty + r;
        if (grow < NNODES) {
            float di = g_dinv[grow];
            float di2 = di * di;
#pragma unroll
            for (int c = 0; c < 4; c++) {
                int col = tx + 32 * c;
                float v = acc[r][c];
                g_h1[(size_t)grow * HID + col] = v;
                g_agg1[(size_t)grow * HID + col] = b1[col] + di2 * v;
            }
        }
    }
}

// ---------------- K4: layer-1 edge scatter (warp per edge, red.v4) ----------------
__global__ __launch_bounds__(256) void k_scatter1() {
    int warp = (blockIdx.x * blockDim.x + threadIdx.x) >> 5;
    int lane = threadIdx.x & 31;
    if (warp >= NEDGES) return;
    int s = g_src[warp];
    int d = g_dst[warp];
    float w = g_dinv[s] * g_dinv[d];
    float4 v = *(const float4*)(g_h1 + (size_t)s * HID + lane * 4);
    float* p = g_agg1 + (size_t)d * HID + lane * 4;
    asm volatile("red.global.add.v4.f32 [%0], {%1, %2, %3, %4};"
                 :: "l"(p), "f"(w * v.x), "f"(w * v.y), "f"(w * v.z), "f"(w * v.w)
                 : "memory");
}

// ---------------- K5: h2 = relu(agg1) @ W2 (warp per node) ----------------
__global__ __launch_bounds__(256) void k_gemm2(const float* __restrict__ W2) {
    __shared__ float W2t[OUTC * HID];  // transposed [oc][k]
    for (int i = threadIdx.x; i < HID * OUTC; i += blockDim.x) {
        int k = i / OUTC, oc = i % OUTC;
        W2t[oc * HID + k] = W2[i];
    }
    __syncthreads();
    int node = (blockIdx.x * blockDim.x + threadIdx.x) >> 5;
    int lane = threadIdx.x & 31;
    if (node >= NNODES) return;

    float4 a = *(const float4*)(g_agg1 + (size_t)node * HID + lane * 4);
    a.x = fmaxf(a.x, 0.f); a.y = fmaxf(a.y, 0.f);
    a.z = fmaxf(a.z, 0.f); a.w = fmaxf(a.w, 0.f);

    float p[OUTC];
#pragma unroll
    for (int oc = 0; oc < OUTC; oc++) {
        float4 wv = *(const float4*)(W2t + oc * HID + lane * 4);
        p[oc] = a.x * wv.x + a.y * wv.y + a.z * wv.z + a.w * wv.w;
    }
#pragma unroll
    for (int off = 16; off; off >>= 1)
#pragma unroll
        for (int oc = 0; oc < OUTC; oc++)
            p[oc] += __shfl_xor_sync(0xffffffffu, p[oc], off);
    if (lane < OUTC) {
        float v = 0.f;
#pragma unroll
        for (int oc = 0; oc < OUTC; oc++)
            if (lane == oc) v = p[oc];
        g_h2[(size_t)node * OUTC + lane] = v;
    }
}

// ---------------- K5b: agg2 = b2 + dinv^2 * h2 ----------------
__global__ void k_init_agg2(const float* __restrict__ b2) {
    int t = blockIdx.x * blockDim.x + threadIdx.x;
    if (t < NNODES * OUTC) {
        int i = t / OUTC, oc = t - i * OUTC;
        float di = g_dinv[i];
        g_agg2[t] = b2[oc] + di * di * g_h2[t];
    }
}

// ---------------- K6: layer-2 edge scatter (thread per edge, red.v2 x9) ----------------
__global__ __launch_bounds__(256) void k_scatter2() {
    int e = blockIdx.x * blockDim.x + threadIdx.x;
    if (e >= NEDGES) return;
    int s = g_src[e];
    int d = g_dst[e];
    float w = g_dinv[s] * g_dinv[d];
    const float2* hp = (const float2*)(g_h2 + (size_t)s * OUTC);
    float* ap = g_agg2 + (size_t)d * OUTC;
#pragma unroll
    for (int j = 0; j < OUTC / 2; j++) {
        float2 v = hp[j];
        asm volatile("red.global.add.v2.f32 [%0], {%1, %2};"
                     :: "l"(ap + 2 * j), "f"(w * v.x), "f"(w * v.y)
                     : "memory");
    }
}

// ---------------- K7: log_softmax per node ----------------
__global__ void k_logsoftmax(float* __restrict__ out) {
    int i = blockIdx.x * blockDim.x + threadIdx.x;
    if (i >= NNODES) return;
    float v[OUTC];
    const float2* rp = (const float2*)(g_agg2 + (size_t)i * OUTC);
#pragma unroll
    for (int j = 0; j < OUTC / 2; j++) {
        float2 t = rp[j];
        v[2 * j] = t.x; v[2 * j + 1] = t.y;
    }
    float m = v[0];
#pragma unroll
    for (int j = 1; j < OUTC; j++) m = fmaxf(m, v[j]);
    float ssum = 0.f;
#pragma unroll
    for (int j = 0; j < OUTC; j++) ssum += expf(v[j] - m);
    float ls = m + logf(ssum);
#pragma unroll
    for (int j = 0; j < OUTC; j++)
        out[(size_t)i * OUTC + j] = v[j] - ls;
}

// ---------------- launch ----------------
extern "C" void kernel_launch(void* const* d_in, const int* in_sizes, int n_in,
                              void* d_out, int out_size) {
    // Map inputs by element count (all distinct) — robust to ordering.
    const float* x = 0; const void* ei = 0;
    const float* W1 = 0; const float* b1 = 0;
    const float* W2 = 0; const float* b2 = 0;
    for (int i = 0; i < n_in; i++) {
        long long sz = in_sizes[i];
        if (sz == (long long)NNODES * INC) x = (const float*)d_in[i];
        else if (sz == 2LL * NEDGES)       ei = d_in[i];
        else if (sz == (long long)INC * HID) W1 = (const float*)d_in[i];
        else if (sz == HID)                b1 = (const float*)d_in[i];
        else if (sz == (long long)HID * OUTC) W2 = (const float*)d_in[i];
        else if (sz == OUTC)               b2 = (const float*)d_in[i];
    }
    float* out = (float*)d_out;

    k_detect<<<1, 32>>>((const unsigned int*)ei);
    k_convert<<<(NEDGES + 255) / 256, 256>>>(ei);
    k_init_deg<<<(NNODES + 255) / 256, 256>>>();
    k_degree<<<(NEDGES + 255) / 256, 256>>>();
    k_dinv<<<(NNODES + 255) / 256, 256>>>();
    k_gemm1<<<(NNODES + 31) / 32, 256>>>(x, W1, b1);
    {
        long long thr = (long long)NEDGES * 32;
        k_scatter1<<<(unsigned)((thr + 255) / 256), 256>>>();
    }
    {
        long long thr = (long long)NNODES * 32;
        k_gemm2<<<(unsigned)((thr + 255) / 256), 256>>>(W2);
    }
    k_init_agg2<<<(NNODES * OUTC + 255) / 256, 256>>>(b2);
    k_scatter2<<<(NEDGES + 255) / 256, 256>>>();
    k_logsoftmax<<<(NNODES + 255) / 256, 256>>>(out);
}

// round 3
// speedup vs baseline: 1.5765x; 1.5765x over previous
#include <cuda_runtime.h>
#include <math.h>

#define NNODES 100000
#define NEDGES 1600000
#define INC 128
#define HID 128
#define OUTC 18
#define NB 98   // ceil(NNODES/1024)

// ---------------- scratch ----------------
__device__ __align__(16) float g_dinv[NNODES];
__device__ __align__(16) float g_h1[(size_t)NNODES * HID];   // x @ W1
__device__ __align__(16) float g_h2[(size_t)NNODES * OUTC];  // layer-2 pre-agg feats
__device__ int g_src[NEDGES];
__device__ int g_dst[NEDGES];
__device__ int g_degi[NNODES];
__device__ int g_rowstart[NNODES + 1];
__device__ int g_cursor[NNODES];
__device__ int g_csrc[NEDGES];       // CSR: src per (dst-sorted) slot
__device__ float g_cw[NEDGES];       // CSR: dinv[src] per slot
__device__ int g_bsum[128];
__device__ int g_is64;

// ---------------- dtype detect ----------------
__global__ void k_detect(const unsigned int* __restrict__ eiw) {
    if (threadIdx.x == 0 && blockIdx.x == 0) {
        int all0 = 1;
        for (int i = 0; i < 128; i++)
            if (eiw[2 * i + 1] != 0u) { all0 = 0; break; }
        g_is64 = all0;
    }
}

// ---------------- convert + zero degree ----------------
__global__ void k_convert(const void* __restrict__ ei) {
    int e = blockIdx.x * blockDim.x + threadIdx.x;
    if (e < NNODES) g_degi[e] = 0;
    if (e >= NEDGES) return;
    if (g_is64) {
        const long long* p = (const long long*)ei;
        g_src[e] = (int)p[e];
        g_dst[e] = (int)p[NEDGES + e];
    } else {
        const int* p = (const int*)ei;
        g_src[e] = p[e];
        g_dst[e] = p[NEDGES + e];
    }
}

// ---------------- degree count (int) ----------------
__global__ void k_count() {
    int e = blockIdx.x * blockDim.x + threadIdx.x;
    if (e < NEDGES) atomicAdd(&g_degi[g_dst[e]], 1);
}

// ---------------- dinv = rsqrt(1 + deg) ----------------
__global__ void k_dinv() {
    int i = blockIdx.x * blockDim.x + threadIdx.x;
    if (i < NNODES) g_dinv[i] = rsqrtf(1.0f + (float)g_degi[i]);
}

// ---------------- exclusive scan (3-phase) ----------------
__global__ __launch_bounds__(1024) void k_scan1() {
    __shared__ int sh[1024];
    int i = blockIdx.x * 1024 + threadIdx.x;
    int v = (i < NNODES) ? g_degi[i] : 0;
    sh[threadIdx.x] = v;
    __syncthreads();
    for (int off = 1; off < 1024; off <<= 1) {
        int t = (threadIdx.x >= off) ? sh[threadIdx.x - off] : 0;
        __syncthreads();
        sh[threadIdx.x] += t;
        __syncthreads();
    }
    if (i < NNODES) g_rowstart[i] = sh[threadIdx.x] - v;  // exclusive
    if (threadIdx.x == 1023) g_bsum[blockIdx.x] = sh[1023];
}
__global__ void k_scan2() {
    if (threadIdx.x == 0 && blockIdx.x == 0) {
        int acc = 0;
        for (int b = 0; b < NB; b++) { int t = g_bsum[b]; g_bsum[b] = acc; acc += t; }
    }
}
__global__ void k_scan3() {
    int i = blockIdx.x * blockDim.x + threadIdx.x;
    if (i < NNODES) {
        int r = g_rowstart[i] + g_bsum[i >> 10];
        g_rowstart[i] = r;
        g_cursor[i] = r;
    }
    if (i == 0) g_rowstart[NNODES] = NEDGES;
}

// ---------------- CSR fill (weight pre-baked) ----------------
__global__ void k_fill() {
    int e = blockIdx.x * blockDim.x + threadIdx.x;
    if (e >= NEDGES) return;
    int s = g_src[e];
    int d = g_dst[e];
    int pos = atomicAdd(&g_cursor[d], 1);
    g_csrc[pos] = s;
    g_cw[pos] = g_dinv[s];
}

// ---------------- GEMM1: h1 = x @ W1 ----------------
__global__ __launch_bounds__(256) void k_gemm1(const float* __restrict__ x,
                                               const float* __restrict__ W1) {
    __shared__ float Ws[64 * 128];
    __shared__ float Xs[32 * 64];
    const int row0 = blockIdx.x * 32;
    const int tid = threadIdx.x;
    const int tx = tid & 31;
    const int ty = tid >> 5;

    float acc[4][4];
#pragma unroll
    for (int r = 0; r < 4; r++)
#pragma unroll
        for (int c = 0; c < 4; c++) acc[r][c] = 0.0f;

    for (int kp = 0; kp < 2; kp++) {
        for (int i = tid; i < 64 * 128 / 4; i += 256)
            ((float4*)Ws)[i] = ((const float4*)(W1 + kp * 64 * 128))[i];
        for (int i = tid; i < 32 * 64 / 4; i += 256) {
            int r = i >> 4, c4 = i & 15;
            int grow = row0 + r;
            float4 v = make_float4(0.f, 0.f, 0.f, 0.f);
            if (grow < NNODES)
                v = *(const float4*)(x + (size_t)grow * INC + kp * 64 + c4 * 4);
            ((float4*)Xs)[i] = v;
        }
        __syncthreads();
#pragma unroll 4
        for (int k = 0; k < 64; k++) {
            float wv[4], xv[4];
#pragma unroll
            for (int c = 0; c < 4; c++) wv[c] = Ws[k * 128 + tx + 32 * c];
#pragma unroll
            for (int r = 0; r < 4; r++) xv[r] = Xs[(4 * ty + r) * 64 + k];
#pragma unroll
            for (int r = 0; r < 4; r++)
#pragma unroll
                for (int c = 0; c < 4; c++) acc[r][c] = fmaf(xv[r], wv[c], acc[r][c]);
        }
        __syncthreads();
    }
#pragma unroll
    for (int r = 0; r < 4; r++) {
        int grow = row0 + 4 * ty + r;
        if (grow < NNODES) {
#pragma unroll
            for (int c = 0; c < 4; c++)
                g_h1[(size_t)grow * HID + tx + 32 * c] = acc[r][c];
        }
    }
}

// ---------------- Layer 1 fused: CSR gather + b1 + self-loop + ReLU + GEMM2 -> h2 ----------------
// warp per node; lane holds cols [4*lane, 4*lane+4)
__global__ __launch_bounds__(256) void k_layer1(const float* __restrict__ b1,
                                                const float* __restrict__ W2) {
    __shared__ float W2t[OUTC * HID];  // [oc][k]
    for (int i = threadIdx.x; i < HID * OUTC; i += blockDim.x) {
        int k = i / OUTC, oc = i % OUTC;
        W2t[oc * HID + k] = W2[i];
    }
    __syncthreads();

    int node = (blockIdx.x * blockDim.x + threadIdx.x) >> 5;
    int lane = threadIdx.x & 31;
    if (node >= NNODES) return;

    float din = g_dinv[node];
    int rs = g_rowstart[node];
    int re = g_rowstart[node + 1];

    // self-loop + bias
    float4 hs = *(const float4*)(g_h1 + (size_t)node * HID + lane * 4);
    float di2 = din * din;
    float4 acc;
    const float4 bv = *(const float4*)(b1 + lane * 4);
    acc.x = bv.x + di2 * hs.x; acc.y = bv.y + di2 * hs.y;
    acc.z = bv.z + di2 * hs.z; acc.w = bv.w + di2 * hs.w;

    for (int base = rs; base < re; base += 32) {
        int j = base + lane;
        int sN = (j < re) ? g_csrc[j] : 0;
        float wN = (j < re) ? g_cw[j] : 0.0f;
        int cnt = min(32, re - base);
        int t = 0;
        for (; t + 4 <= cnt; t += 4) {
            int s0 = __shfl_sync(0xffffffffu, sN, t);
            int s1 = __shfl_sync(0xffffffffu, sN, t + 1);
            int s2 = __shfl_sync(0xffffffffu, sN, t + 2);
            int s3 = __shfl_sync(0xffffffffu, sN, t + 3);
            float w0 = __shfl_sync(0xffffffffu, wN, t) * din;
            float w1 = __shfl_sync(0xffffffffu, wN, t + 1) * din;
            float w2 = __shfl_sync(0xffffffffu, wN, t + 2) * din;
            float w3 = __shfl_sync(0xffffffffu, wN, t + 3) * din;
            float4 v0 = *(const float4*)(g_h1 + (size_t)s0 * HID + lane * 4);
            float4 v1 = *(const float4*)(g_h1 + (size_t)s1 * HID + lane * 4);
            float4 v2 = *(const float4*)(g_h1 + (size_t)s2 * HID + lane * 4);
            float4 v3 = *(const float4*)(g_h1 + (size_t)s3 * HID + lane * 4);
            acc.x = fmaf(w0, v0.x, acc.x); acc.y = fmaf(w0, v0.y, acc.y);
            acc.z = fmaf(w0, v0.z, acc.z); acc.w = fmaf(w0, v0.w, acc.w);
            acc.x = fmaf(w1, v1.x, acc.x); acc.y = fmaf(w1, v1.y, acc.y);
            acc.z = fmaf(w1, v1.z, acc.z); acc.w = fmaf(w1, v1.w, acc.w);
            acc.x = fmaf(w2, v2.x, acc.x); acc.y = fmaf(w2, v2.y, acc.y);
            acc.z = fmaf(w2, v2.z, acc.z); acc.w = fmaf(w2, v2.w, acc.w);
            acc.x = fmaf(w3, v3.x, acc.x); acc.y = fmaf(w3, v3.y, acc.y);
            acc.z = fmaf(w3, v3.z, acc.z); acc.w = fmaf(w3, v3.w, acc.w);
        }
        for (; t < cnt; t++) {
            int ss = __shfl_sync(0xffffffffu, sN, t);
            float w = __shfl_sync(0xffffffffu, wN, t) * din;
            float4 v = *(const float4*)(g_h1 + (size_t)ss * HID + lane * 4);
            acc.x = fmaf(w, v.x, acc.x); acc.y = fmaf(w, v.y, acc.y);
            acc.z = fmaf(w, v.z, acc.z); acc.w = fmaf(w, v.w, acc.w);
        }
    }

    // ReLU
    acc.x = fmaxf(acc.x, 0.f); acc.y = fmaxf(acc.y, 0.f);
    acc.z = fmaxf(acc.z, 0.f); acc.w = fmaxf(acc.w, 0.f);

    // GEMM2: p[oc] = sum_k relu(agg)[k] * W2[k][oc]
    float p[OUTC];
#pragma unroll
    for (int oc = 0; oc < OUTC; oc++) {
        const float4 wv = *(const float4*)(W2t + oc * HID + lane * 4);
        p[oc] = acc.x * wv.x + acc.y * wv.y + acc.z * wv.z + acc.w * wv.w;
    }
#pragma unroll
    for (int off = 16; off; off >>= 1)
#pragma unroll
        for (int oc = 0; oc < OUTC; oc++)
            p[oc] += __shfl_xor_sync(0xffffffffu, p[oc], off);
    if (lane < OUTC) {
        float v = 0.f;
#pragma unroll
        for (int oc = 0; oc < OUTC; oc++)
            if (lane == oc) v = p[oc];
        g_h2[(size_t)node * OUTC + lane] = v;
    }
}

// ---------------- Layer 2 fused: CSR gather + b2 + self-loop + log_softmax -> out ----------------
__global__ __launch_bounds__(256) void k_layer2(const float* __restrict__ b2,
                                                float* __restrict__ out) {
    int node = (blockIdx.x * blockDim.x + threadIdx.x) >> 5;
    int lane = threadIdx.x & 31;
    if (node >= NNODES) return;

    float din = g_dinv[node];
    int rs = g_rowstart[node];
    int re = g_rowstart[node + 1];

    float acc = 0.0f;
    if (lane < OUTC)
        acc = b2[lane] + din * din * g_h2[(size_t)node * OUTC + lane];

    for (int base = rs; base < re; base += 32) {
        int j = base + lane;
        int sN = (j < re) ? g_csrc[j] : 0;
        float wN = (j < re) ? g_cw[j] : 0.0f;
        int cnt = min(32, re - base);
        int t = 0;
        for (; t + 4 <= cnt; t += 4) {
            int s0 = __shfl_sync(0xffffffffu, sN, t);
            int s1 = __shfl_sync(0xffffffffu, sN, t + 1);
            int s2 = __shfl_sync(0xffffffffu, sN, t + 2);
            int s3 = __shfl_sync(0xffffffffu, sN, t + 3);
            float w0 = __shfl_sync(0xffffffffu, wN, t) * din;
            float w1 = __shfl_sync(0xffffffffu, wN, t + 1) * din;
            float w2 = __shfl_sync(0xffffffffu, wN, t + 2) * din;
            float w3 = __shfl_sync(0xffffffffu, wN, t + 3) * din;
            float v0 = 0.f, v1 = 0.f, v2 = 0.f, v3 = 0.f;
            if (lane < OUTC) {
                v0 = g_h2[(size_t)s0 * OUTC + lane];
                v1 = g_h2[(size_t)s1 * OUTC + lane];
                v2 = g_h2[(size_t)s2 * OUTC + lane];
                v3 = g_h2[(size_t)s3 * OUTC + lane];
            }
            acc = fmaf(w0, v0, acc);
            acc = fmaf(w1, v1, acc);
            acc = fmaf(w2, v2, acc);
            acc = fmaf(w3, v3, acc);
        }
        for (; t < cnt; t++) {
            int ss = __shfl_sync(0xffffffffu, sN, t);
            float w = __shfl_sync(0xffffffffu, wN, t) * din;
            float v = (lane < OUTC) ? g_h2[(size_t)ss * OUTC + lane] : 0.f;
            acc = fmaf(w, v, acc);
        }
    }

    // log_softmax over 18 lanes
    float m = (lane < OUTC) ? acc : -1e30f;
#pragma unroll
    for (int off = 16; off; off >>= 1)
        m = fmaxf(m, __shfl_xor_sync(0xffffffffu, m, off));
    float e = (lane < OUTC) ? expf(acc - m) : 0.f;
#pragma unroll
    for (int off = 16; off; off >>= 1)
        e += __shfl_xor_sync(0xffffffffu, e, off);
    float ls = m + logf(e);
    if (lane < OUTC)
        out[(size_t)node * OUTC + lane] = acc - ls;
}

// ---------------- launch ----------------
extern "C" void kernel_launch(void* const* d_in, const int* in_sizes, int n_in,
                              void* d_out, int out_size) {
    const float* x = 0; const void* ei = 0;
    const float* W1 = 0; const float* b1 = 0;
    const float* W2 = 0; const float* b2 = 0;
    for (int i = 0; i < n_in; i++) {
        long long sz = in_sizes[i];
        if (sz == (long long)NNODES * INC) x = (const float*)d_in[i];
        else if (sz == 2LL * NEDGES)       ei = d_in[i];
        else if (sz == (long long)INC * HID) W1 = (const float*)d_in[i];
        else if (sz == HID)                b1 = (const float*)d_in[i];
        else if (sz == (long long)HID * OUTC) W2 = (const float*)d_in[i];
        else if (sz == OUTC)               b2 = (const float*)d_in[i];
    }
    float* out = (float*)d_out;

    k_detect<<<1, 32>>>((const unsigned int*)ei);
    k_convert<<<(NEDGES + 255) / 256, 256>>>(ei);
    k_count<<<(NEDGES + 255) / 256, 256>>>();
    k_dinv<<<(NNODES + 255) / 256, 256>>>();
    k_scan1<<<NB, 1024>>>();
    k_scan2<<<1, 32>>>();
    k_scan3<<<(NNODES + 255) / 256, 256>>>();
    k_fill<<<(NEDGES + 255) / 256, 256>>>();
    k_gemm1<<<(NNODES + 31) / 32, 256>>>(x, W1);
    {
        long long thr = (long long)NNODES * 32;
        k_layer1<<<(unsigned)((thr + 255) / 256), 256>>>(b1, W2);
        k_layer2<<<(unsigned)((thr + 255) / 256), 256>>>(b2, out);
    }
}

// round 4
// speedup vs baseline: 1.5940x; 1.0111x over previous
#include <cuda_runtime.h>
#include <cuda_fp16.h>
#include <math.h>

#define NNODES 100000
#define NEDGES 1600000
#define INC 128
#define HID 128
#define OUTC 18
#define NB 98   // ceil(NNODES/1024)

// ---------------- scratch ----------------
__device__ __align__(16) float g_dinv[NNODES];
__device__ __align__(16) __half g_h1h[(size_t)NNODES * HID];   // x @ W1, fp16
__device__ __align__(16) __half g_h2h[(size_t)NNODES * OUTC];  // layer-2 feats, fp16
__device__ int g_src[NEDGES];
__device__ int g_dst[NEDGES];
__device__ int g_degi[NNODES];
__device__ int g_rowstart[NNODES + 1];
__device__ int g_cursor[NNODES];
__device__ int g_csrc[NEDGES];
__device__ float g_cw[NEDGES];
__device__ int g_bsum[128];
__device__ int g_is64;

// ---------------- dtype detect ----------------
__global__ void k_detect(const unsigned int* __restrict__ eiw) {
    if (threadIdx.x == 0 && blockIdx.x == 0) {
        int all0 = 1;
        for (int i = 0; i < 128; i++)
            if (eiw[2 * i + 1] != 0u) { all0 = 0; break; }
        g_is64 = all0;
    }
}

// ---------------- zero degree ----------------
__global__ void k_zero() {
    int i = blockIdx.x * blockDim.x + threadIdx.x;
    if (i < NNODES) g_degi[i] = 0;
}

// ---------------- convert + count fused ----------------
__global__ void k_convert_count(const void* __restrict__ ei) {
    int e = blockIdx.x * blockDim.x + threadIdx.x;
    if (e >= NEDGES) return;
    int s, d;
    if (g_is64) {
        const long long* p = (const long long*)ei;
        s = (int)p[e];
        d = (int)p[NEDGES + e];
    } else {
        const int* p = (const int*)ei;
        s = p[e];
        d = p[NEDGES + e];
    }
    g_src[e] = s;
    g_dst[e] = d;
    atomicAdd(&g_degi[d], 1);
}

// ---------------- exclusive scan (3-phase); scan3 also computes dinv ----------------
__global__ __launch_bounds__(1024) void k_scan1() {
    __shared__ int sh[1024];
    int i = blockIdx.x * 1024 + threadIdx.x;
    int v = (i < NNODES) ? g_degi[i] : 0;
    sh[threadIdx.x] = v;
    __syncthreads();
    for (int off = 1; off < 1024; off <<= 1) {
        int t = (threadIdx.x >= off) ? sh[threadIdx.x - off] : 0;
        __syncthreads();
        sh[threadIdx.x] += t;
        __syncthreads();
    }
    if (i < NNODES) g_rowstart[i] = sh[threadIdx.x] - v;
    if (threadIdx.x == 1023) g_bsum[blockIdx.x] = sh[1023];
}
__global__ void k_scan2() {
    if (threadIdx.x == 0 && blockIdx.x == 0) {
        int acc = 0;
        for (int b = 0; b < NB; b++) { int t = g_bsum[b]; g_bsum[b] = acc; acc += t; }
    }
}
__global__ void k_scan3() {
    int i = blockIdx.x * blockDim.x + threadIdx.x;
    if (i < NNODES) {
        int r = g_rowstart[i] + g_bsum[i >> 10];
        g_rowstart[i] = r;
        g_cursor[i] = r;
        g_dinv[i] = rsqrtf(1.0f + (float)g_degi[i]);
    }
    if (i == 0) g_rowstart[NNODES] = NEDGES;
}

// ---------------- CSR fill ----------------
__global__ void k_fill() {
    int e = blockIdx.x * blockDim.x + threadIdx.x;
    if (e >= NEDGES) return;
    int s = g_src[e];
    int d = g_dst[e];
    int pos = atomicAdd(&g_cursor[d], 1);
    g_csrc[pos] = s;
    g_cw[pos] = g_dinv[s];
}

// ---------------- GEMM1: h1 = x @ W1 -> fp16 ----------------
// 256 threads, 64 rows/block. tx=tid&31 -> cols [4tx,4tx+4); ty=tid>>5 -> rows [8ty,8ty+8)
__global__ __launch_bounds__(256) void k_gemm1(const float* __restrict__ x,
                                               const float* __restrict__ W1) {
    __shared__ float Ws[64 * 128];   // 32 KB  [k][col]
    __shared__ float Xs[64 * 64];    // 16 KB  [row][k]
    const int row0 = blockIdx.x * 64;
    const int tid = threadIdx.x;
    const int tx = tid & 31;
    const int ty = tid >> 5;

    float4 acc[8];
#pragma unroll
    for (int r = 0; r < 8; r++) acc[r] = make_float4(0.f, 0.f, 0.f, 0.f);

    for (int kp = 0; kp < 2; kp++) {
        for (int i = tid; i < 64 * 128 / 4; i += 256)
            ((float4*)Ws)[i] = ((const float4*)(W1 + kp * 64 * 128))[i];
        for (int i = tid; i < 64 * 64 / 4; i += 256) {
            int r = i >> 4, c4 = i & 15;
            int grow = row0 + r;
            float4 v = make_float4(0.f, 0.f, 0.f, 0.f);
            if (grow < NNODES)
                v = *(const float4*)(x + (size_t)grow * INC + kp * 64 + c4 * 4);
            ((float4*)Xs)[i] = v;
        }
        __syncthreads();
#pragma unroll 4
        for (int k = 0; k < 64; k += 4) {
            float4 wv[4];
#pragma unroll
            for (int kk = 0; kk < 4; kk++)
                wv[kk] = *(const float4*)(Ws + (k + kk) * 128 + 4 * tx);
#pragma unroll
            for (int r = 0; r < 8; r++) {
                float4 xv = *(const float4*)(Xs + (8 * ty + r) * 64 + k);
                acc[r].x = fmaf(xv.x, wv[0].x, acc[r].x);
                acc[r].y = fmaf(xv.x, wv[0].y, acc[r].y);
                acc[r].z = fmaf(xv.x, wv[0].z, acc[r].z);
                acc[r].w = fmaf(xv.x, wv[0].w, acc[r].w);
                acc[r].x = fmaf(xv.y, wv[1].x, acc[r].x);
                acc[r].y = fmaf(xv.y, wv[1].y, acc[r].y);
                acc[r].z = fmaf(xv.y, wv[1].z, acc[r].z);
                acc[r].w = fmaf(xv.y, wv[1].w, acc[r].w);
                acc[r].x = fmaf(xv.z, wv[2].x, acc[r].x);
                acc[r].y = fmaf(xv.z, wv[2].y, acc[r].y);
                acc[r].z = fmaf(xv.z, wv[2].z, acc[r].z);
                acc[r].w = fmaf(xv.z, wv[2].w, acc[r].w);
                acc[r].x = fmaf(xv.w, wv[3].x, acc[r].x);
                acc[r].y = fmaf(xv.w, wv[3].y, acc[r].y);
                acc[r].z = fmaf(xv.w, wv[3].z, acc[r].z);
                acc[r].w = fmaf(xv.w, wv[3].w, acc[r].w);
            }
        }
        __syncthreads();
    }
#pragma unroll
    for (int r = 0; r < 8; r++) {
        int grow = row0 + 8 * ty + r;
        if (grow < NNODES) {
            __half2 lo = __float22half2_rn(make_float2(acc[r].x, acc[r].y));
            __half2 hi = __float22half2_rn(make_float2(acc[r].z, acc[r].w));
            uint2 u;
            u.x = *(unsigned int*)&lo;
            u.y = *(unsigned int*)&hi;
            *(uint2*)(g_h1h + (size_t)grow * HID + 4 * tx) = u;
        }
    }
}

// ---------------- Layer 1 fused: CSR gather(fp16) + b1 + self + ReLU + GEMM2 -> h2(fp16) ----------------
__global__ __launch_bounds__(256) void k_layer1(const float* __restrict__ b1,
                                                const float* __restrict__ W2) {
    __shared__ float W2t[OUTC * HID];  // [oc][k]
    for (int i = threadIdx.x; i < HID * OUTC; i += blockDim.x) {
        int k = i / OUTC, oc = i % OUTC;
        W2t[oc * HID + k] = W2[i];
    }
    __syncthreads();

    int node = (blockIdx.x * blockDim.x + threadIdx.x) >> 5;
    int lane = threadIdx.x & 31;
    if (node >= NNODES) return;

    float din = g_dinv[node];
    int rs = g_rowstart[node];
    int re = g_rowstart[node + 1];

    // self-loop + bias
    uint2 us = *(const uint2*)(g_h1h + (size_t)node * HID + lane * 4);
    float2 sa = __half22float2(*(__half2*)&us.x);
    float2 sb = __half22float2(*(__half2*)&us.y);
    float di2 = din * din;
    const float4 bv = *(const float4*)(b1 + lane * 4);
    float4 acc;
    acc.x = bv.x + di2 * sa.x; acc.y = bv.y + di2 * sa.y;
    acc.z = bv.z + di2 * sb.x; acc.w = bv.w + di2 * sb.y;

    for (int base = rs; base < re; base += 32) {
        int j = base + lane;
        int sN = (j < re) ? g_csrc[j] : 0;
        float wN = (j < re) ? g_cw[j] : 0.0f;
        int cnt = min(32, re - base);
        int t = 0;
        for (; t + 8 <= cnt; t += 8) {
            uint2 u[8]; float w[8];
#pragma unroll
            for (int q = 0; q < 8; q++) {
                int ss = __shfl_sync(0xffffffffu, sN, t + q);
                w[q] = __shfl_sync(0xffffffffu, wN, t + q) * din;
                u[q] = *(const uint2*)(g_h1h + (size_t)ss * HID + lane * 4);
            }
#pragma unroll
            for (int q = 0; q < 8; q++) {
                float2 fa = __half22float2(*(__half2*)&u[q].x);
                float2 fb = __half22float2(*(__half2*)&u[q].y);
                acc.x = fmaf(w[q], fa.x, acc.x);
                acc.y = fmaf(w[q], fa.y, acc.y);
                acc.z = fmaf(w[q], fb.x, acc.z);
                acc.w = fmaf(w[q], fb.y, acc.w);
            }
        }
        for (; t < cnt; t++) {
            int ss = __shfl_sync(0xffffffffu, sN, t);
            float w = __shfl_sync(0xffffffffu, wN, t) * din;
            uint2 u = *(const uint2*)(g_h1h + (size_t)ss * HID + lane * 4);
            float2 fa = __half22float2(*(__half2*)&u.x);
            float2 fb = __half22float2(*(__half2*)&u.y);
            acc.x = fmaf(w, fa.x, acc.x);
            acc.y = fmaf(w, fa.y, acc.y);
            acc.z = fmaf(w, fb.x, acc.z);
            acc.w = fmaf(w, fb.y, acc.w);
        }
    }

    // ReLU
    acc.x = fmaxf(acc.x, 0.f); acc.y = fmaxf(acc.y, 0.f);
    acc.z = fmaxf(acc.z, 0.f); acc.w = fmaxf(acc.w, 0.f);

    // GEMM2
    float p[OUTC];
#pragma unroll
    for (int oc = 0; oc < OUTC; oc++) {
        const float4 wv = *(const float4*)(W2t + oc * HID + lane * 4);
        p[oc] = acc.x * wv.x + acc.y * wv.y + acc.z * wv.z + acc.w * wv.w;
    }
#pragma unroll
    for (int off = 16; off; off >>= 1)
#pragma unroll
        for (int oc = 0; oc < OUTC; oc++)
            p[oc] += __shfl_xor_sync(0xffffffffu, p[oc], off);
    if (lane < OUTC) {
        float v = 0.f;
#pragma unroll
        for (int oc = 0; oc < OUTC; oc++)
            if (lane == oc) v = p[oc];
        g_h2h[(size_t)node * OUTC + lane] = __float2half_rn(v);
    }
}

// ---------------- Layer 2 fused: CSR gather(fp16) + b2 + self + log_softmax ----------------
__global__ __launch_bounds__(256) void k_layer2(const float* __restrict__ b2,
                                                float* __restrict__ out) {
    int node = (blockIdx.x * blockDim.x + threadIdx.x) >> 5;
    int lane = threadIdx.x & 31;
    if (node >= NNODES) return;

    float din = g_dinv[node];
    int rs = g_rowstart[node];
    int re = g_rowstart[node + 1];

    float acc = 0.0f;
    if (lane < OUTC)
        acc = b2[lane] + din * din * __half2float(g_h2h[(size_t)node * OUTC + lane]);

    for (int base = rs; base < re; base += 32) {
        int j = base + lane;
        int sN = (j < re) ? g_csrc[j] : 0;
        float wN = (j < re) ? g_cw[j] : 0.0f;
        int cnt = min(32, re - base);
        int t = 0;
        for (; t + 8 <= cnt; t += 8) {
            float v[8], w[8];
#pragma unroll
            for (int q = 0; q < 8; q++) {
                int ss = __shfl_sync(0xffffffffu, sN, t + q);
                w[q] = __shfl_sync(0xffffffffu, wN, t + q) * din;
                v[q] = (lane < OUTC) ? __half2float(g_h2h[(size_t)ss * OUTC + lane]) : 0.f;
            }
#pragma unroll
            for (int q = 0; q < 8; q++) acc = fmaf(w[q], v[q], acc);
        }
        for (; t < cnt; t++) {
            int ss = __shfl_sync(0xffffffffu, sN, t);
            float w = __shfl_sync(0xffffffffu, wN, t) * din;
            float v = (lane < OUTC) ? __half2float(g_h2h[(size_t)ss * OUTC + lane]) : 0.f;
            acc = fmaf(w, v, acc);
        }
    }

    // log_softmax over 18 lanes
    float m = (lane < OUTC) ? acc : -1e30f;
#pragma unroll
    for (int off = 16; off; off >>= 1)
        m = fmaxf(m, __shfl_xor_sync(0xffffffffu, m, off));
    float e = (lane < OUTC) ? expf(acc - m) : 0.f;
#pragma unroll
    for (int off = 16; off; off >>= 1)
        e += __shfl_xor_sync(0xffffffffu, e, off);
    float ls = m + logf(e);
    if (lane < OUTC)
        out[(size_t)node * OUTC + lane] = acc - ls;
}

// ---------------- launch ----------------
extern "C" void kernel_launch(void* const* d_in, const int* in_sizes, int n_in,
                              void* d_out, int out_size) {
    const float* x = 0; const void* ei = 0;
    const float* W1 = 0; const float* b1 = 0;
    const float* W2 = 0; const float* b2 = 0;
    for (int i = 0; i < n_in; i++) {
        long long sz = in_sizes[i];
        if (sz == (long long)NNODES * INC) x = (const float*)d_in[i];
        else if (sz == 2LL * NEDGES)       ei = d_in[i];
        else if (sz == (long long)INC * HID) W1 = (const float*)d_in[i];
        else if (sz == HID)                b1 = (const float*)d_in[i];
        else if (sz == (long long)HID * OUTC) W2 = (const float*)d_in[i];
        else if (sz == OUTC)               b2 = (const float*)d_in[i];
    }
    float* out = (float*)d_out;

    k_detect<<<1, 32>>>((const unsigned int*)ei);
    k_zero<<<(NNODES + 255) / 256, 256>>>();
    k_convert_count<<<(NEDGES + 255) / 256, 256>>>(ei);
    k_scan1<<<NB, 1024>>>();
    k_scan2<<<1, 32>>>();
    k_scan3<<<(NNODES + 255) / 256, 256>>>();
    k_fill<<<(NEDGES + 255) / 256, 256>>>();
    k_gemm1<<<(NNODES + 63) / 64, 256>>>(x, W1);
    {
        long long thr = (long long)NNODES * 32;
        k_layer1<<<(unsigned)((thr + 255) / 256), 256>>>(b1, W2);
        k_layer2<<<(unsigned)((thr + 255) / 256), 256>>>(b2, out);
    }
}

// round 6
// speedup vs baseline: 1.8963x; 1.1897x over previous
#include <cuda_runtime.h>
#include <cuda_fp16.h>
#include <math.h>

#define NNODES 100000
#define NEDGES 1600000
#define INC 128
#define HID 128
#define OUTC 18
#define NB 98   // ceil(NNODES/1024)

// ---------------- scratch ----------------
__device__ __align__(16) float g_dinv[NNODES];
__device__ __align__(16) __half g_xh[(size_t)NNODES * INC];    // x in fp16
__device__ __align__(16) __half g_w1h[INC * HID];              // W1 in fp16
__device__ __align__(16) __half g_h1h[(size_t)NNODES * HID];   // x @ W1, fp16
__device__ __align__(16) __half g_h2h[(size_t)NNODES * OUTC];  // layer-2 feats
__device__ int g_src[NEDGES];
__device__ int g_dst[NEDGES];
__device__ int g_degi[NNODES];
__device__ int g_rowstart[NNODES + 1];
__device__ int g_cursor[NNODES];
__device__ int g_csrc[NEDGES];
__device__ float g_cw[NEDGES];
__device__ int g_bsum[128];
__device__ int g_is64;

// ---------------- K1: zero degree + parallel dtype detect ----------------
__global__ void k_prep(const unsigned int* __restrict__ eiw) {
    int i = blockIdx.x * blockDim.x + threadIdx.x;
    if (i < NNODES) g_degi[i] = 0;
    if (blockIdx.x == 0 && threadIdx.x < 32) {
        unsigned int any = 0;
        for (int q = threadIdx.x; q < 128; q += 32) any |= eiw[2 * q + 1];
        unsigned int b = __ballot_sync(0xffffffffu, any != 0u);
        if (threadIdx.x == 0) g_is64 = (b == 0u);
    }
}

// ---------------- K2: convert + degree count ----------------
__global__ void k_convert_count(const void* __restrict__ ei) {
    int e = blockIdx.x * blockDim.x + threadIdx.x;
    if (e >= NEDGES) return;
    int s, d;
    if (g_is64) {
        const long long* p = (const long long*)ei;
        s = (int)p[e];
        d = (int)p[NEDGES + e];
    } else {
        const int* p = (const int*)ei;
        s = p[e];
        d = p[NEDGES + e];
    }
    g_src[e] = s;
    g_dst[e] = d;
    atomicAdd(&g_degi[d], 1);
}

// ---------------- K3: fp32 -> fp16 for x and W1 ----------------
__global__ void k_tofp16(const float* __restrict__ x, const float* __restrict__ W1) {
    int i = blockIdx.x * blockDim.x + threadIdx.x;  // float4 index
    if (i < NNODES * INC / 4) {
        float4 v = ((const float4*)x)[i];
        __half2 lo = __floats2half2_rn(v.x, v.y);
        __half2 hi = __floats2half2_rn(v.z, v.w);
        uint2 u;
        u.x = *(unsigned int*)&lo;
        u.y = *(unsigned int*)&hi;
        *(uint2*)(g_xh + (size_t)i * 4) = u;
    }
    if (i < INC * HID / 4) {
        float4 v = ((const float4*)W1)[i];
        __half2 lo = __floats2half2_rn(v.x, v.y);
        __half2 hi = __floats2half2_rn(v.z, v.w);
        uint2 u;
        u.x = *(unsigned int*)&lo;
        u.y = *(unsigned int*)&hi;
        *(uint2*)(g_w1h + (size_t)i * 4) = u;
    }
}

// ---------------- K4: GEMM1 via tensor cores ----------------
// block: 256 thr (8 warps), tile 128 rows x 128 cols, k in 2 phases of 64.
// warp w handles rows [16w,16w+16). Per warp: 16 n8-tiles accumulators.
#define XS_STRIDE 144   // bytes per row: 64 halfs + 8 pad = 72*2
#define WS_STRIDE 272   // bytes per row: 128 halfs + 8 pad = 136*2
__global__ __launch_bounds__(256) void k_gemm1_mma() {
    __shared__ __align__(16) unsigned char s_x[128 * XS_STRIDE];  // 18432 B
    __shared__ __align__(16) unsigned char s_w[64 * WS_STRIDE];   // 17408 B

    const int tid = threadIdx.x;
    const int wid = tid >> 5;
    const int lane = tid & 31;
    const int row0 = blockIdx.x * 128;

    float acc[16][4];
#pragma unroll
    for (int t = 0; t < 16; t++)
#pragma unroll
        for (int q = 0; q < 4; q++) acc[t][q] = 0.0f;

    for (int kp = 0; kp < 2; kp++) {
        // load X tile: 128 rows x 64 halfs
        for (int i = tid; i < 128 * 8; i += 256) {
            int r = i >> 3, c = i & 7;
            uint4 v = make_uint4(0u, 0u, 0u, 0u);
            if (row0 + r < NNODES)
                v = *(const uint4*)(g_xh + (size_t)(row0 + r) * INC + kp * 64 + c * 8);
            *(uint4*)(s_x + r * XS_STRIDE + c * 16) = v;
        }
        // load W tile: 64 k-rows x 128 halfs
        for (int i = tid; i < 64 * 16; i += 256) {
            int r = i >> 4, c = i & 15;
            uint4 v = *(const uint4*)(g_w1h + (size_t)(kp * 64 + r) * HID + c * 8);
            *(uint4*)(s_w + r * WS_STRIDE + c * 16) = v;
        }
        __syncthreads();

#pragma unroll
        for (int kk = 0; kk < 4; kk++) {
            // A fragment: 16x16 from s_x rows [16*wid, +16), cols [16*kk, +16)
            unsigned int a0, a1, a2, a3;
            {
                const unsigned char* p = s_x + (wid * 16 + (lane & 15)) * XS_STRIDE
                                             + kk * 32 + (lane >> 4) * 16;
                unsigned int sa = (unsigned int)__cvta_generic_to_shared(p);
                asm volatile("ldmatrix.sync.aligned.m8n8.x4.shared.b16 {%0,%1,%2,%3}, [%4];"
                             : "=r"(a0), "=r"(a1), "=r"(a2), "=r"(a3) : "r"(sa));
            }
#pragma unroll
            for (int j = 0; j < 8; j++) {
                // B fragments for n-tiles 2j, 2j+1: k16 x n16 with trans
                unsigned int b0, b1, b2, b3;
                const unsigned char* p = s_w + (kk * 16 + (lane & 15)) * WS_STRIDE
                                             + j * 32 + (lane >> 4) * 16;
                unsigned int sb = (unsigned int)__cvta_generic_to_shared(p);
                asm volatile("ldmatrix.sync.aligned.m8n8.x4.trans.shared.b16 {%0,%1,%2,%3}, [%4];"
                             : "=r"(b0), "=r"(b1), "=r"(b2), "=r"(b3) : "r"(sb));
                asm volatile("mma.sync.aligned.m16n8k16.row.col.f32.f16.f16.f32 "
                             "{%0,%1,%2,%3}, {%4,%5,%6,%7}, {%8,%9}, {%0,%1,%2,%3};"
                             : "+f"(acc[2 * j][0]), "+f"(acc[2 * j][1]),
                               "+f"(acc[2 * j][2]), "+f"(acc[2 * j][3])
                             : "r"(a0), "r"(a1), "r"(a2), "r"(a3), "r"(b0), "r"(b1));
                asm volatile("mma.sync.aligned.m16n8k16.row.col.f32.f16.f16.f32 "
                             "{%0,%1,%2,%3}, {%4,%5,%6,%7}, {%8,%9}, {%0,%1,%2,%3};"
                             : "+f"(acc[2 * j + 1][0]), "+f"(acc[2 * j + 1][1]),
                               "+f"(acc[2 * j + 1][2]), "+f"(acc[2 * j + 1][3])
                             : "r"(a0), "r"(a1), "r"(a2), "r"(a3), "r"(b2), "r"(b3));
            }
        }
        __syncthreads();
    }

    // epilogue: thread owns D[gr][gc,gc+1] and D[gr+8][gc,gc+1] per tile
    int gr = lane >> 2;
    int gc = (lane & 3) * 2;
    int r1 = row0 + wid * 16 + gr;
    int r2 = r1 + 8;
#pragma unroll
    for (int t = 0; t < 16; t++) {
        int col = t * 8 + gc;
        if (r1 < NNODES) {
            __half2 h = __floats2half2_rn(acc[t][0], acc[t][1]);
            *(__half2*)(g_h1h + (size_t)r1 * HID + col) = h;
        }
        if (r2 < NNODES) {
            __half2 h = __floats2half2_rn(acc[t][2], acc[t][3]);
            *(__half2*)(g_h1h + (size_t)r2 * HID + col) = h;
        }
    }
}

// ---------------- scan (3-phase), scan2 parallelized ----------------
__global__ __launch_bounds__(1024) void k_scan1() {
    __shared__ int sh[1024];
    int i = blockIdx.x * 1024 + threadIdx.x;
    int v = (i < NNODES) ? g_degi[i] : 0;
    sh[threadIdx.x] = v;
    __syncthreads();
    for (int off = 1; off < 1024; off <<= 1) {
        int t = (threadIdx.x >= off) ? sh[threadIdx.x - off] : 0;
        __syncthreads();
        sh[threadIdx.x] += t;
        __syncthreads();
    }
    if (i < NNODES) g_rowstart[i] = sh[threadIdx.x] - v;
    if (threadIdx.x == 1023) g_bsum[blockIdx.x] = sh[1023];
}
__global__ void k_scan2p() {
    __shared__ int sh[128];
    int t = threadIdx.x;
    int v = (t < NB) ? g_bsum[t] : 0;
    sh[t] = v;
    __syncthreads();
    for (int off = 1; off < 128; off <<= 1) {
        int u = (t >= off) ? sh[t - off] : 0;
        __syncthreads();
        sh[t] += u;
        __syncthreads();
    }
    if (t < NB) g_bsum[t] = sh[t] - v;  // exclusive
}
__global__ void k_scan3() {
    int i = blockIdx.x * blockDim.x + threadIdx.x;
    if (i < NNODES) {
        int r = g_rowstart[i] + g_bsum[i >> 10];
        g_rowstart[i] = r;
        g_cursor[i] = r;
        g_dinv[i] = rsqrtf(1.0f + (float)g_degi[i]);
    }
    if (i == 0) g_rowstart[NNODES] = NEDGES;
}

// ---------------- CSR fill ----------------
__global__ void k_fill() {
    int e = blockIdx.x * blockDim.x + threadIdx.x;
    if (e >= NEDGES) return;
    int s = g_src[e];
    int d = g_dst[e];
    int pos = atomicAdd(&g_cursor[d], 1);
    g_csrc[pos] = s;
    g_cw[pos] = g_dinv[s];
}

// ---------------- Layer 1 fused: gather(fp16) + b1 + self + ReLU + GEMM2 -> h2(fp16) ----------------
__global__ __launch_bounds__(256) void k_layer1(const float* __restrict__ b1,
                                                const float* __restrict__ W2) {
    __shared__ float W2t[OUTC * HID];  // [oc][k]
    for (int i = threadIdx.x; i < HID * OUTC; i += blockDim.x) {
        int k = i / OUTC, oc = i % OUTC;
        W2t[oc * HID + k] = W2[i];
    }
    __syncthreads();

    int node = (blockIdx.x * blockDim.x + threadIdx.x) >> 5;
    int lane = threadIdx.x & 31;
    if (node >= NNODES) return;

    float din = g_dinv[node];
    int rs = g_rowstart[node];
    int re = g_rowstart[node + 1];

    uint2 us = *(const uint2*)(g_h1h + (size_t)node * HID + lane * 4);
    float2 sa = __half22float2(*(__half2*)&us.x);
    float2 sb = __half22float2(*(__half2*)&us.y);
    float di2 = din * din;
    const float4 bv = *(const float4*)(b1 + lane * 4);
    float4 acc;
    acc.x = bv.x + di2 * sa.x; acc.y = bv.y + di2 * sa.y;
    acc.z = bv.z + di2 * sb.x; acc.w = bv.w + di2 * sb.y;

    for (int base = rs; base < re; base += 32) {
        int j = base + lane;
        int sN = (j < re) ? g_csrc[j] : 0;
        float wN = (j < re) ? g_cw[j] : 0.0f;
        int cnt = min(32, re - base);
        int t = 0;
        for (; t + 8 <= cnt; t += 8) {
            uint2 u[8]; float w[8];
#pragma unroll
            for (int q = 0; q < 8; q++) {
                int ss = __shfl_sync(0xffffffffu, sN, t + q);
                w[q] = __shfl_sync(0xffffffffu, wN, t + q) * din;
                u[q] = *(const uint2*)(g_h1h + (size_t)ss * HID + lane * 4);
            }
#pragma unroll
            for (int q = 0; q < 8; q++) {
                float2 fa = __half22float2(*(__half2*)&u[q].x);
                float2 fb = __half22float2(*(__half2*)&u[q].y);
                acc.x = fmaf(w[q], fa.x, acc.x);
                acc.y = fmaf(w[q], fa.y, acc.y);
                acc.z = fmaf(w[q], fb.x, acc.z);
                acc.w = fmaf(w[q], fb.y, acc.w);
            }
        }
        for (; t < cnt; t++) {
            int ss = __shfl_sync(0xffffffffu, sN, t);
            float w = __shfl_sync(0xffffffffu, wN, t) * din;
            uint2 u = *(const uint2*)(g_h1h + (size_t)ss * HID + lane * 4);
            float2 fa = __half22float2(*(__half2*)&u.x);
            float2 fb = __half22float2(*(__half2*)&u.y);
            acc.x = fmaf(w, fa.x, acc.x);
            acc.y = fmaf(w, fa.y, acc.y);
            acc.z = fmaf(w, fb.x, acc.z);
            acc.w = fmaf(w, fb.y, acc.w);
        }
    }

    acc.x = fmaxf(acc.x, 0.f); acc.y = fmaxf(acc.y, 0.f);
    acc.z = fmaxf(acc.z, 0.f); acc.w = fmaxf(acc.w, 0.f);

    float p[OUTC];
#pragma unroll
    for (int oc = 0; oc < OUTC; oc++) {
        const float4 wv = *(const float4*)(W2t + oc * HID + lane * 4);
        p[oc] = acc.x * wv.x + acc.y * wv.y + acc.z * wv.z + acc.w * wv.w;
    }
#pragma unroll
    for (int off = 16; off; off >>= 1)
#pragma unroll
        for (int oc = 0; oc < OUTC; oc++)
            p[oc] += __shfl_xor_sync(0xffffffffu, p[oc], off);
    if (lane < OUTC) {
        float v = 0.f;
#pragma unroll
        for (int oc = 0; oc < OUTC; oc++)
            if (lane == oc) v = p[oc];
        g_h2h[(size_t)node * OUTC + lane] = __float2half_rn(v);
    }
}

// ---------------- Layer 2 fused: gather(fp16) + b2 + self + log_softmax ----------------
__global__ __launch_bounds__(256) void k_layer2(const float* __restrict__ b2,
                                                float* __restrict__ out) {
    int node = (blockIdx.x * blockDim.x + threadIdx.x) >> 5;
    int lane = threadIdx.x & 31;
    if (node >= NNODES) return;

    float din = g_dinv[node];
    int rs = g_rowstart[node];
    int re = g_rowstart[node + 1];

    float acc = 0.0f;
    if (lane < OUTC)
        acc = b2[lane] + din * din * __half2float(g_h2h[(size_t)node * OUTC + lane]);

    for (int base = rs; base < re; base += 32) {
        int j = base + lane;
        int sN = (j < re) ? g_csrc[j] : 0;
        float wN = (j < re) ? g_cw[j] : 0.0f;
        int cnt = min(32, re - base);
        int t = 0;
        for (; t + 8 <= cnt; t += 8) {
            float v[8], w[8];
#pragma unroll
            for (int q = 0; q < 8; q++) {
                int ss = __shfl_sync(0xffffffffu, sN, t + q);
                w[q] = __shfl_sync(0xffffffffu, wN, t + q) * din;
                v[q] = (lane < OUTC) ? __half2float(g_h2h[(size_t)ss * OUTC + lane]) : 0.f;
            }
#pragma unroll
            for (int q = 0; q < 8; q++) acc = fmaf(w[q], v[q], acc);
        }
        for (; t < cnt; t++) {
            int ss = __shfl_sync(0xffffffffu, sN, t);
            float w = __shfl_sync(0xffffffffu, wN, t) * din;
            float v = (lane < OUTC) ? __half2float(g_h2h[(size_t)ss * OUTC + lane]) : 0.f;
            acc = fmaf(w, v, acc);
        }
    }

    float m = (lane < OUTC) ? acc : -1e30f;
#pragma unroll
    for (int off = 16; off; off >>= 1)
        m = fmaxf(m, __shfl_xor_sync(0xffffffffu, m, off));
    float e = (lane < OUTC) ? expf(acc - m) : 0.f;
#pragma unroll
    for (int off = 16; off; off >>= 1)
        e += __shfl_xor_sync(0xffffffffu, e, off);
    float ls = m + logf(e);
    if (lane < OUTC)
        out[(size_t)node * OUTC + lane] = acc - ls;
}

// ---------------- launch ----------------
extern "C" void kernel_launch(void* const* d_in, const int* in_sizes, int n_in,
                              void* d_out, int out_size) {
    const float* x = 0; const void* ei = 0;
    const float* W1 = 0; const float* b1 = 0;
    const float* W2 = 0; const float* b2 = 0;
    for (int i = 0; i < n_in; i++) {
        long long sz = in_sizes[i];
        if (sz == (long long)NNODES * INC) x = (const float*)d_in[i];
        else if (sz == 2LL * NEDGES)       ei = d_in[i];
        else if (sz == (long long)INC * HID) W1 = (const float*)d_in[i];
        else if (sz == HID)                b1 = (const float*)d_in[i];
        else if (sz == (long long)HID * OUTC) W2 = (const float*)d_in[i];
        else if (sz == OUTC)               b2 = (const float*)d_in[i];
    }
    float* out = (float*)d_out;

    k_prep<<<(NNODES + 255) / 256, 256>>>((const unsigned int*)ei);          // 1
    k_convert_count<<<(NEDGES + 255) / 256, 256>>>(ei);                       // 2
    k_tofp16<<<(NNODES * INC / 4 + 255) / 256, 256>>>(x, W1);                 // 3
    k_gemm1_mma<<<(NNODES + 127) / 128, 256>>>();                             // 4 (profiled)
    k_scan1<<<NB, 1024>>>();                                                  // 5
    k_scan2p<<<1, 128>>>();                                                   // 6
    k_scan3<<<(NNODES + 255) / 256, 256>>>();                                 // 7
    k_fill<<<(NEDGES + 255) / 256, 256>>>();                                  // 8
    {
        long long thr = (long long)NNODES * 32;
        k_layer1<<<(unsigned)((thr + 255) / 256), 256>>>(b1, W2);             // 9
        k_layer2<<<(unsigned)((thr + 255) / 256), 256>>>(b2, out);            // 10
    }
}

// round 7
// speedup vs baseline: 2.2843x; 1.2046x over previous
#include <cuda_runtime.h>
#include <cuda_fp16.h>
#include <math.h>

#define NNODES 100000
#define NEDGES 1600000
#define INC 128
#define HID 128
#define OUTC 18
#define NB 98   // ceil(NNODES/1024)
#define W2S 132 // padded W2t row stride (floats)

// ---------------- scratch ----------------
__device__ __align__(16) float g_dinv[NNODES];
__device__ __align__(16) __half g_xh[(size_t)NNODES * INC];    // x in fp16
__device__ __align__(16) __half g_w1h[INC * HID];              // W1 in fp16
__device__ __align__(16) __half g_h1h[(size_t)NNODES * HID];   // x @ W1, fp16
__device__ __align__(16) __half g_h2h[(size_t)NNODES * OUTC];  // layer-2 feats
__device__ int g_degi[NNODES];
__device__ int g_rowstart[NNODES + 1];
__device__ int g_cursor[NNODES];
__device__ __align__(8) int2 g_cadj[NEDGES];   // packed CSR: {src, dinv[src] bits}
__device__ int g_bsum[128];
__device__ int g_is64;

// ---------------- K1: zero degree + dtype detect + fp16 convert ----------------
__global__ void k_prep(const unsigned int* __restrict__ eiw,
                       const float* __restrict__ x, const float* __restrict__ W1) {
    int i = blockIdx.x * blockDim.x + threadIdx.x;
    if (i < NNODES) g_degi[i] = 0;
    if (blockIdx.x == 0 && threadIdx.x < 32) {
        unsigned int any = 0;
        for (int q = threadIdx.x; q < 128; q += 32) any |= eiw[2 * q + 1];
        unsigned int b = __ballot_sync(0xffffffffu, any != 0u);
        if (threadIdx.x == 0) g_is64 = (b == 0u);
    }
    if (i < NNODES * INC / 4) {
        float4 v = ((const float4*)x)[i];
        __half2 lo = __floats2half2_rn(v.x, v.y);
        __half2 hi = __floats2half2_rn(v.z, v.w);
        uint2 u;
        u.x = *(unsigned int*)&lo;
        u.y = *(unsigned int*)&hi;
        *(uint2*)(g_xh + (size_t)i * 4) = u;
    }
    if (i < INC * HID / 4) {
        float4 v = ((const float4*)W1)[i];
        __half2 lo = __floats2half2_rn(v.x, v.y);
        __half2 hi = __floats2half2_rn(v.z, v.w);
        uint2 u;
        u.x = *(unsigned int*)&lo;
        u.y = *(unsigned int*)&hi;
        *(uint2*)(g_w1h + (size_t)i * 4) = u;
    }
}

// ---------------- K2: degree count straight from edge buffer ----------------
__global__ void k_count(const void* __restrict__ ei) {
    int e = blockIdx.x * blockDim.x + threadIdx.x;
    if (e >= NEDGES) return;
    int d;
    if (g_is64) d = (int)((const long long*)ei)[NEDGES + e];
    else        d = ((const int*)ei)[NEDGES + e];
    atomicAdd(&g_degi[d], 1);
}

// ---------------- scan phase 1 ----------------
__global__ __launch_bounds__(1024) void k_scan1() {
    __shared__ int sh[1024];
    int i = blockIdx.x * 1024 + threadIdx.x;
    int v = (i < NNODES) ? g_degi[i] : 0;
    sh[threadIdx.x] = v;
    __syncthreads();
    for (int off = 1; off < 1024; off <<= 1) {
        int t = (threadIdx.x >= off) ? sh[threadIdx.x - off] : 0;
        __syncthreads();
        sh[threadIdx.x] += t;
        __syncthreads();
    }
    if (i < NNODES) g_rowstart[i] = sh[threadIdx.x] - v;
    if (threadIdx.x == 1023) g_bsum[blockIdx.x] = sh[1023];
}

// ---------------- K4: GEMM1 via tensor cores (unchanged; profiled slot) ----------------
#define XS_STRIDE 144
#define WS_STRIDE 272
__global__ __launch_bounds__(256) void k_gemm1_mma() {
    __shared__ __align__(16) unsigned char s_x[128 * XS_STRIDE];
    __shared__ __align__(16) unsigned char s_w[64 * WS_STRIDE];

    const int tid = threadIdx.x;
    const int wid = tid >> 5;
    const int lane = tid & 31;
    const int row0 = blockIdx.x * 128;

    float acc[16][4];
#pragma unroll
    for (int t = 0; t < 16; t++)
#pragma unroll
        for (int q = 0; q < 4; q++) acc[t][q] = 0.0f;

    for (int kp = 0; kp < 2; kp++) {
        for (int i = tid; i < 128 * 8; i += 256) {
            int r = i >> 3, c = i & 7;
            uint4 v = make_uint4(0u, 0u, 0u, 0u);
            if (row0 + r < NNODES)
                v = *(const uint4*)(g_xh + (size_t)(row0 + r) * INC + kp * 64 + c * 8);
            *(uint4*)(s_x + r * XS_STRIDE + c * 16) = v;
        }
        for (int i = tid; i < 64 * 16; i += 256) {
            int r = i >> 4, c = i & 15;
            uint4 v = *(const uint4*)(g_w1h + (size_t)(kp * 64 + r) * HID + c * 8);
            *(uint4*)(s_w + r * WS_STRIDE + c * 16) = v;
        }
        __syncthreads();

#pragma unroll
        for (int kk = 0; kk < 4; kk++) {
            unsigned int a0, a1, a2, a3;
            {
                const unsigned char* p = s_x + (wid * 16 + (lane & 15)) * XS_STRIDE
                                             + kk * 32 + (lane >> 4) * 16;
                unsigned int sa = (unsigned int)__cvta_generic_to_shared(p);
                asm volatile("ldmatrix.sync.aligned.m8n8.x4.shared.b16 {%0,%1,%2,%3}, [%4];"
                             : "=r"(a0), "=r"(a1), "=r"(a2), "=r"(a3) : "r"(sa));
            }
#pragma unroll
            for (int j = 0; j < 8; j++) {
                unsigned int b0, b1, b2, b3;
                const unsigned char* p = s_w + (kk * 16 + (lane & 15)) * WS_STRIDE
                                             + j * 32 + (lane >> 4) * 16;
                unsigned int sb = (unsigned int)__cvta_generic_to_shared(p);
                asm volatile("ldmatrix.sync.aligned.m8n8.x4.trans.shared.b16 {%0,%1,%2,%3}, [%4];"
                             : "=r"(b0), "=r"(b1), "=r"(b2), "=r"(b3) : "r"(sb));
                asm volatile("mma.sync.aligned.m16n8k16.row.col.f32.f16.f16.f32 "
                             "{%0,%1,%2,%3}, {%4,%5,%6,%7}, {%8,%9}, {%0,%1,%2,%3};"
                             : "+f"(acc[2 * j][0]), "+f"(acc[2 * j][1]),
                               "+f"(acc[2 * j][2]), "+f"(acc[2 * j][3])
                             : "r"(a0), "r"(a1), "r"(a2), "r"(a3), "r"(b0), "r"(b1));
                asm volatile("mma.sync.aligned.m16n8k16.row.col.f32.f16.f16.f32 "
                             "{%0,%1,%2,%3}, {%4,%5,%6,%7}, {%8,%9}, {%0,%1,%2,%3};"
                             : "+f"(acc[2 * j + 1][0]), "+f"(acc[2 * j + 1][1]),
                               "+f"(acc[2 * j + 1][2]), "+f"(acc[2 * j + 1][3])
                             : "r"(a0), "r"(a1), "r"(a2), "r"(a3), "r"(b2), "r"(b3));
            }
        }
        __syncthreads();
    }

    int gr = lane >> 2;
    int gc = (lane & 3) * 2;
    int r1 = row0 + wid * 16 + gr;
    int r2 = r1 + 8;
#pragma unroll
    for (int t = 0; t < 16; t++) {
        int col = t * 8 + gc;
        if (r1 < NNODES) {
            __half2 h = __floats2half2_rn(acc[t][0], acc[t][1]);
            *(__half2*)(g_h1h + (size_t)r1 * HID + col) = h;
        }
        if (r2 < NNODES) {
            __half2 h = __floats2half2_rn(acc[t][2], acc[t][3]);
            *(__half2*)(g_h1h + (size_t)r2 * HID + col) = h;
        }
    }
}

// ---------------- scan phases 2,3 ----------------
__global__ void k_scan2p() {
    __shared__ int sh[128];
    int t = threadIdx.x;
    int v = (t < NB) ? g_bsum[t] : 0;
    sh[t] = v;
    __syncthreads();
    for (int off = 1; off < 128; off <<= 1) {
        int u = (t >= off) ? sh[t - off] : 0;
        __syncthreads();
        sh[t] += u;
        __syncthreads();
    }
    if (t < NB) g_bsum[t] = sh[t] - v;
}
__global__ void k_scan3() {
    int i = blockIdx.x * blockDim.x + threadIdx.x;
    if (i < NNODES) {
        int r = g_rowstart[i] + g_bsum[i >> 10];
        g_rowstart[i] = r;
        g_cursor[i] = r;
        g_dinv[i] = rsqrtf(1.0f + (float)g_degi[i]);
    }
    if (i == 0) g_rowstart[NNODES] = NEDGES;
}

// ---------------- CSR fill (packed, reads edge buffer directly) ----------------
__global__ void k_fill(const void* __restrict__ ei) {
    int e = blockIdx.x * blockDim.x + threadIdx.x;
    if (e >= NEDGES) return;
    int s, d;
    if (g_is64) {
        const long long* p = (const long long*)ei;
        s = (int)p[e];
        d = (int)p[NEDGES + e];
    } else {
        const int* p = (const int*)ei;
        s = p[e];
        d = p[NEDGES + e];
    }
    int pos = atomicAdd(&g_cursor[d], 1);
    g_cadj[pos] = make_int2(s, __float_as_int(g_dinv[s]));
}

// ---------------- Layer 1 fused: gather + b1 + self + ReLU + smem-GEMM2 -> h2 ----------------
__global__ __launch_bounds__(256) void k_layer1(const float* __restrict__ b1,
                                                const float* __restrict__ W2) {
    __shared__ float W2t[OUTC * W2S];   // [oc][k], padded stride
    __shared__ float s_agg[8][HID];     // per-warp staging
    for (int i = threadIdx.x; i < HID * OUTC; i += blockDim.x) {
        int k = i / OUTC, oc = i % OUTC;
        W2t[oc * W2S + k] = W2[i];
    }
    __syncthreads();

    int node = (blockIdx.x * blockDim.x + threadIdx.x) >> 5;
    int lane = threadIdx.x & 31;
    int wid = (threadIdx.x >> 5);
    if (node >= NNODES) return;

    float din = g_dinv[node];
    int rs = g_rowstart[node];
    int re = g_rowstart[node + 1];

    // self-loop + bias
    uint2 us = *(const uint2*)(g_h1h + (size_t)node * HID + lane * 4);
    float2 sa = __half22float2(*(__half2*)&us.x);
    float2 sb = __half22float2(*(__half2*)&us.y);
    float di2 = din * din;
    const float4 bv = *(const float4*)(b1 + lane * 4);
    float4 acc;
    acc.x = bv.x + di2 * sa.x; acc.y = bv.y + di2 * sa.y;
    acc.z = bv.z + di2 * sb.x; acc.w = bv.w + di2 * sb.y;

    for (int base = rs; base < re; base += 32) {
        int j = base + lane;
        int2 ew = (j < re) ? g_cadj[j] : make_int2(0, 0);
        int cnt = min(32, re - base);
        int t = 0;
        for (; t + 8 <= cnt; t += 8) {
            uint2 u[8]; float w[8];
#pragma unroll
            for (int q = 0; q < 8; q++) {
                int ss = __shfl_sync(0xffffffffu, ew.x, t + q);
                int wb = __shfl_sync(0xffffffffu, ew.y, t + q);
                w[q] = __int_as_float(wb) * din;
                u[q] = *(const uint2*)(g_h1h + (size_t)ss * HID + lane * 4);
            }
#pragma unroll
            for (int q = 0; q < 8; q++) {
                float2 fa = __half22float2(*(__half2*)&u[q].x);
                float2 fb = __half22float2(*(__half2*)&u[q].y);
                acc.x = fmaf(w[q], fa.x, acc.x);
                acc.y = fmaf(w[q], fa.y, acc.y);
                acc.z = fmaf(w[q], fb.x, acc.z);
                acc.w = fmaf(w[q], fb.y, acc.w);
            }
        }
        for (; t < cnt; t++) {
            int ss = __shfl_sync(0xffffffffu, ew.x, t);
            int wb = __shfl_sync(0xffffffffu, ew.y, t);
            float w = __int_as_float(wb) * din;
            uint2 u = *(const uint2*)(g_h1h + (size_t)ss * HID + lane * 4);
            float2 fa = __half22float2(*(__half2*)&u.x);
            float2 fb = __half22float2(*(__half2*)&u.y);
            acc.x = fmaf(w, fa.x, acc.x);
            acc.y = fmaf(w, fa.y, acc.y);
            acc.z = fmaf(w, fb.x, acc.z);
            acc.w = fmaf(w, fb.y, acc.w);
        }
    }

    // ReLU + stage to smem
    acc.x = fmaxf(acc.x, 0.f); acc.y = fmaxf(acc.y, 0.f);
    acc.z = fmaxf(acc.z, 0.f); acc.w = fmaxf(acc.w, 0.f);
    *(float4*)&s_agg[wid][lane * 4] = acc;
    __syncwarp();

    // GEMM2: 18 lanes each compute a full 128-dot (smem broadcast + padded W2t)
    if (lane < OUTC) {
        float p = 0.f;
#pragma unroll
        for (int k = 0; k < HID; k += 4) {
            const float4 a = *(const float4*)&s_agg[wid][k];
            const float4 w = *(const float4*)&W2t[lane * W2S + k];
            p += a.x * w.x + a.y * w.y + a.z * w.z + a.w * w.w;
        }
        g_h2h[(size_t)node * OUTC + lane] = __float2half_rn(p);
    }
}

// ---------------- Layer 2 fused: gather + b2 + self + log_softmax ----------------
__global__ __launch_bounds__(256) void k_layer2(const float* __restrict__ b2,
                                                float* __restrict__ out) {
    int node = (blockIdx.x * blockDim.x + threadIdx.x) >> 5;
    int lane = threadIdx.x & 31;
    if (node >= NNODES) return;

    float din = g_dinv[node];
    int rs = g_rowstart[node];
    int re = g_rowstart[node + 1];

    float acc = 0.0f;
    if (lane < OUTC)
        acc = b2[lane] + din * din * __half2float(g_h2h[(size_t)node * OUTC + lane]);

    for (int base = rs; base < re; base += 32) {
        int j = base + lane;
        int2 ew = (j < re) ? g_cadj[j] : make_int2(0, 0);
        int cnt = min(32, re - base);
        int t = 0;
        for (; t + 8 <= cnt; t += 8) {
            float v[8], w[8];
#pragma unroll
            for (int q = 0; q < 8; q++) {
                int ss = __shfl_sync(0xffffffffu, ew.x, t + q);
                int wb = __shfl_sync(0xffffffffu, ew.y, t + q);
                w[q] = __int_as_float(wb) * din;
                v[q] = (lane < OUTC) ? __half2float(g_h2h[(size_t)ss * OUTC + lane]) : 0.f;
            }
#pragma unroll
            for (int q = 0; q < 8; q++) acc = fmaf(w[q], v[q], acc);
        }
        for (; t < cnt; t++) {
            int ss = __shfl_sync(0xffffffffu, ew.x, t);
            int wb = __shfl_sync(0xffffffffu, ew.y, t);
            float w = __int_as_float(wb) * din;
            float v = (lane < OUTC) ? __half2float(g_h2h[(size_t)ss * OUTC + lane]) : 0.f;
            acc = fmaf(w, v, acc);
        }
    }

    float m = (lane < OUTC) ? acc : -1e30f;
#pragma unroll
    for (int off = 16; off; off >>= 1)
        m = fmaxf(m, __shfl_xor_sync(0xffffffffu, m, off));
    float e = (lane < OUTC) ? expf(acc - m) : 0.f;
#pragma unroll
    for (int off = 16; off; off >>= 1)
        e += __shfl_xor_sync(0xffffffffu, e, off);
    float ls = m + logf(e);
    if (lane < OUTC)
        out[(size_t)node * OUTC + lane] = acc - ls;
}

// ---------------- launch ----------------
extern "C" void kernel_launch(void* const* d_in, const int* in_sizes, int n_in,
                              void* d_out, int out_size) {
    const float* x = 0; const void* ei = 0;
    const float* W1 = 0; const float* b1 = 0;
    const float* W2 = 0; const float* b2 = 0;
    for (int i = 0; i < n_in; i++) {
        long long sz = in_sizes[i];
        if (sz == (long long)NNODES * INC) x = (const float*)d_in[i];
        else if (sz == 2LL * NEDGES)       ei = d_in[i];
        else if (sz == (long long)INC * HID) W1 = (const float*)d_in[i];
        else if (sz == HID)                b1 = (const float*)d_in[i];
        else if (sz == (long long)HID * OUTC) W2 = (const float*)d_in[i];
        else if (sz == OUTC)               b2 = (const float*)d_in[i];
    }
    float* out = (float*)d_out;

    k_prep<<<(NNODES * INC / 4 + 255) / 256, 256>>>((const unsigned int*)ei, x, W1); // 1
    k_count<<<(NEDGES + 255) / 256, 256>>>(ei);                                      // 2
    k_scan1<<<NB, 1024>>>();                                                         // 3
    k_gemm1_mma<<<(NNODES + 127) / 128, 256>>>();                                    // 4 (profiled)
    k_scan2p<<<1, 128>>>();                                                          // 5
    k_scan3<<<(NNODES + 255) / 256, 256>>>();                                        // 6
    k_fill<<<(NEDGES + 255) / 256, 256>>>(ei);                                       // 7
    {
        long long thr = (long long)NNODES * 32;
        k_layer1<<<(unsigned)((thr + 255) / 256), 256>>>(b1, W2);                    // 8
        k_layer2<<<(unsigned)((thr + 255) / 256), 256>>>(b2, out);                   // 9
    }
}

// round 8
// speedup vs baseline: 2.3770x; 1.0406x over previous
#include <cuda_runtime.h>
#include <cuda_fp16.h>
#include <math.h>

#define NNODES 100000
#define NEDGES 1600000
#define INC 128
#define HID 128
#define OUTC 18
#define NB 98   // ceil(NNODES/1024)
#define W2S 132 // padded W2t row stride (floats)

// ---------------- scratch ----------------
__device__ __align__(16) float g_dinv[NNODES];
__device__ __align__(16) __half g_xh[(size_t)NNODES * INC];
__device__ __align__(16) __half g_w1h[INC * HID];
__device__ __align__(16) __half g_h1h[(size_t)NNODES * HID];
__device__ __align__(16) __half g_h2h[(size_t)NNODES * OUTC];
__device__ int g_degi[NNODES];
__device__ int g_rowstart[NNODES + 1];
__device__ int g_cursor[NNODES];
__device__ __align__(8) int2 g_cadj[NEDGES];   // {src, dinv[src] bits}
__device__ int g_bsum[128];
__device__ int g_is64;

// ---------------- K1: zero degree + dtype detect + fp16 convert ----------------
__global__ void k_prep(const unsigned int* __restrict__ eiw,
                       const float* __restrict__ x, const float* __restrict__ W1) {
    int i = blockIdx.x * blockDim.x + threadIdx.x;
    if (i < NNODES) g_degi[i] = 0;
    if (blockIdx.x == 0 && threadIdx.x < 32) {
        unsigned int any = 0;
        for (int q = threadIdx.x; q < 128; q += 32) any |= eiw[2 * q + 1];
        unsigned int b = __ballot_sync(0xffffffffu, any != 0u);
        if (threadIdx.x == 0) g_is64 = (b == 0u);
    }
    if (i < NNODES * INC / 4) {
        float4 v = ((const float4*)x)[i];
        __half2 lo = __floats2half2_rn(v.x, v.y);
        __half2 hi = __floats2half2_rn(v.z, v.w);
        uint2 u;
        u.x = *(unsigned int*)&lo;
        u.y = *(unsigned int*)&hi;
        *(uint2*)(g_xh + (size_t)i * 4) = u;
    }
    if (i < INC * HID / 4) {
        float4 v = ((const float4*)W1)[i];
        __half2 lo = __floats2half2_rn(v.x, v.y);
        __half2 hi = __floats2half2_rn(v.z, v.w);
        uint2 u;
        u.x = *(unsigned int*)&lo;
        u.y = *(unsigned int*)&hi;
        *(uint2*)(g_w1h + (size_t)i * 4) = u;
    }
}

// ---------------- K2: degree count ----------------
__global__ void k_count(const void* __restrict__ ei) {
    int e = blockIdx.x * blockDim.x + threadIdx.x;
    if (e >= NEDGES) return;
    int d;
    if (g_is64) d = (int)((const long long*)ei)[NEDGES + e];
    else        d = ((const int*)ei)[NEDGES + e];
    atomicAdd(&g_degi[d], 1);
}

// ---------------- scan phase 1 ----------------
__global__ __launch_bounds__(1024) void k_scan1() {
    __shared__ int sh[1024];
    int i = blockIdx.x * 1024 + threadIdx.x;
    int v = (i < NNODES) ? g_degi[i] : 0;
    sh[threadIdx.x] = v;
    __syncthreads();
    for (int off = 1; off < 1024; off <<= 1) {
        int t = (threadIdx.x >= off) ? sh[threadIdx.x - off] : 0;
        __syncthreads();
        sh[threadIdx.x] += t;
        __syncthreads();
    }
    if (i < NNODES) g_rowstart[i] = sh[threadIdx.x] - v;
    if (threadIdx.x == 1023) g_bsum[blockIdx.x] = sh[1023];
}

// ---------------- K4: GEMM1 tensor cores + cp.async double buffer ----------------
#define XS_STRIDE 144
#define WS_STRIDE 272
#define SX_BYTES (128 * XS_STRIDE)   // 18432
#define SW_BYTES (64 * WS_STRIDE)    // 17408
#define PHASE_BYTES (SX_BYTES + SW_BYTES)
#define GEMM1_SMEM (2 * PHASE_BYTES) // 71680

__device__ __forceinline__ void cp16(unsigned int dst, const void* src, int srcsize) {
    asm volatile("cp.async.cg.shared.global [%0], [%1], 16, %2;"
                 :: "r"(dst), "l"(src), "r"(srcsize));
}

__global__ __launch_bounds__(256) void k_gemm1_mma() {
    extern __shared__ __align__(16) unsigned char dynsmem[];
    const int tid = threadIdx.x;
    const int wid = tid >> 5;
    const int lane = tid & 31;
    const int row0 = blockIdx.x * 128;

    // issue async loads for both phases
#pragma unroll
    for (int kp = 0; kp < 2; kp++) {
        unsigned char* s_x = dynsmem + kp * PHASE_BYTES;
        unsigned char* s_w = s_x + SX_BYTES;
        for (int i = tid; i < 128 * 8; i += 256) {
            int r = i >> 3, c = i & 7;
            const void* src = g_xh + (size_t)(row0 + r) * INC + kp * 64 + c * 8;
            int vsz = (row0 + r < NNODES) ? 16 : 0;
            unsigned int dst = (unsigned int)__cvta_generic_to_shared(s_x + r * XS_STRIDE + c * 16);
            cp16(dst, src, vsz);
        }
        for (int i = tid; i < 64 * 16; i += 256) {
            int r = i >> 4, c = i & 15;
            const void* src = g_w1h + (size_t)(kp * 64 + r) * HID + c * 8;
            unsigned int dst = (unsigned int)__cvta_generic_to_shared(s_w + r * WS_STRIDE + c * 16);
            cp16(dst, src, 16);
        }
        asm volatile("cp.async.commit_group;");
    }

    float acc[16][4];
#pragma unroll
    for (int t = 0; t < 16; t++)
#pragma unroll
        for (int q = 0; q < 4; q++) acc[t][q] = 0.0f;

#pragma unroll
    for (int kp = 0; kp < 2; kp++) {
        if (kp == 0) asm volatile("cp.async.wait_group 1;");
        else         asm volatile("cp.async.wait_group 0;");
        __syncthreads();
        unsigned char* s_x = dynsmem + kp * PHASE_BYTES;
        unsigned char* s_w = s_x + SX_BYTES;

#pragma unroll
        for (int kk = 0; kk < 4; kk++) {
            unsigned int a0, a1, a2, a3;
            {
                const unsigned char* p = s_x + (wid * 16 + (lane & 15)) * XS_STRIDE
                                             + kk * 32 + (lane >> 4) * 16;
                unsigned int sa = (unsigned int)__cvta_generic_to_shared(p);
                asm volatile("ldmatrix.sync.aligned.m8n8.x4.shared.b16 {%0,%1,%2,%3}, [%4];"
                             : "=r"(a0), "=r"(a1), "=r"(a2), "=r"(a3) : "r"(sa));
            }
#pragma unroll
            for (int j = 0; j < 8; j++) {
                unsigned int b0, b1, b2, b3;
                const unsigned char* p = s_w + (kk * 16 + (lane & 15)) * WS_STRIDE
                                             + j * 32 + (lane >> 4) * 16;
                unsigned int sb = (unsigned int)__cvta_generic_to_shared(p);
                asm volatile("ldmatrix.sync.aligned.m8n8.x4.trans.shared.b16 {%0,%1,%2,%3}, [%4];"
                             : "=r"(b0), "=r"(b1), "=r"(b2), "=r"(b3) : "r"(sb));
                asm volatile("mma.sync.aligned.m16n8k16.row.col.f32.f16.f16.f32 "
                             "{%0,%1,%2,%3}, {%4,%5,%6,%7}, {%8,%9}, {%0,%1,%2,%3};"
                             : "+f"(acc[2 * j][0]), "+f"(acc[2 * j][1]),
                               "+f"(acc[2 * j][2]), "+f"(acc[2 * j][3])
                             : "r"(a0), "r"(a1), "r"(a2), "r"(a3), "r"(b0), "r"(b1));
                asm volatile("mma.sync.aligned.m16n8k16.row.col.f32.f16.f16.f32 "
                             "{%0,%1,%2,%3}, {%4,%5,%6,%7}, {%8,%9}, {%0,%1,%2,%3};"
                             : "+f"(acc[2 * j + 1][0]), "+f"(acc[2 * j + 1][1]),
                               "+f"(acc[2 * j + 1][2]), "+f"(acc[2 * j + 1][3])
                             : "r"(a0), "r"(a1), "r"(a2), "r"(a3), "r"(b2), "r"(b3));
            }
        }
        __syncthreads();
    }

    int gr = lane >> 2;
    int gc = (lane & 3) * 2;
    int r1 = row0 + wid * 16 + gr;
    int r2 = r1 + 8;
#pragma unroll
    for (int t = 0; t < 16; t++) {
        int col = t * 8 + gc;
        if (r1 < NNODES) {
            __half2 h = __floats2half2_rn(acc[t][0], acc[t][1]);
            *(__half2*)(g_h1h + (size_t)r1 * HID + col) = h;
        }
        if (r2 < NNODES) {
            __half2 h = __floats2half2_rn(acc[t][2], acc[t][3]);
            *(__half2*)(g_h1h + (size_t)r2 * HID + col) = h;
        }
    }
}

// ---------------- scan phases 2+3 fused ----------------
__global__ __launch_bounds__(256) void k_scan3f() {
    __shared__ int sh[128];
    int t = threadIdx.x;
    int v0 = 0;
    if (t < 128) {
        v0 = (t < NB) ? g_bsum[t] : 0;
        sh[t] = v0;
    }
    __syncthreads();
    for (int off = 1; off < 128; off <<= 1) {
        int u = (t < 128 && t >= off) ? sh[t - off] : 0;
        __syncthreads();
        if (t < 128) sh[t] += u;
        __syncthreads();
    }
    if (t < 128) {
        int ex = sh[t] - v0;
        __syncthreads();
        sh[t] = ex;
    }
    __syncthreads();
    int i = blockIdx.x * 256 + t;
    if (i < NNODES) {
        int r = g_rowstart[i] + sh[i >> 10];
        g_rowstart[i] = r;
        g_cursor[i] = r;
        g_dinv[i] = rsqrtf(1.0f + (float)g_degi[i]);
    }
    if (i == 0) g_rowstart[NNODES] = NEDGES;
}

// ---------------- CSR fill ----------------
__global__ void k_fill(const void* __restrict__ ei) {
    int e = blockIdx.x * blockDim.x + threadIdx.x;
    if (e >= NEDGES) return;
    int s, d;
    if (g_is64) {
        const long long* p = (const long long*)ei;
        s = (int)p[e];
        d = (int)p[NEDGES + e];
    } else {
        const int* p = (const int*)ei;
        s = p[e];
        d = p[NEDGES + e];
    }
    int pos = atomicAdd(&g_cursor[d], 1);
    g_cadj[pos] = make_int2(s, __float_as_int(g_dinv[s]));
}

// ---------------- Layer 1: 2 nodes/warp, 16 lanes/node, LDG.128 gathers ----------------
__global__ __launch_bounds__(256) void k_layer1(const float* __restrict__ b1,
                                                const float* __restrict__ W2) {
    __shared__ float W2t[OUTC * W2S];
    __shared__ float s_agg[16][HID];
    for (int i = threadIdx.x; i < HID * OUTC; i += blockDim.x) {
        int k = i / OUTC, oc = i % OUTC;
        W2t[oc * W2S + k] = W2[i];
    }
    __syncthreads();

    const int wid = threadIdx.x >> 5;
    const int lane = threadIdx.x & 31;
    const int h = lane >> 4;
    const int hl = lane & 15;
    const unsigned hmask = h ? 0xffff0000u : 0x0000ffffu;
    const int node = blockIdx.x * 16 + wid * 2 + h;

    if (node < NNODES) {
        float din = g_dinv[node];
        int rs = g_rowstart[node];
        int re = g_rowstart[node + 1];

        // self-loop + bias: this lane owns cols [8*hl, 8*hl+8)
        uint4 us = *(const uint4*)(g_h1h + (size_t)node * HID + hl * 8);
        const __half2* up = (const __half2*)&us;
        float2 f0 = __half22float2(up[0]), f1 = __half22float2(up[1]);
        float2 f2 = __half22float2(up[2]), f3 = __half22float2(up[3]);
        float di2 = din * din;
        float4 ba = *(const float4*)(b1 + hl * 8);
        float4 bb = *(const float4*)(b1 + hl * 8 + 4);
        float4 acc0, acc1;
        acc0.x = ba.x + di2 * f0.x; acc0.y = ba.y + di2 * f0.y;
        acc0.z = ba.z + di2 * f1.x; acc0.w = ba.w + di2 * f1.y;
        acc1.x = bb.x + di2 * f2.x; acc1.y = bb.y + di2 * f2.y;
        acc1.z = bb.z + di2 * f3.x; acc1.w = bb.w + di2 * f3.y;

        for (int base = rs; base < re; base += 16) {
            int j = base + hl;
            int2 ew = (j < re) ? g_cadj[j] : make_int2(0, 0);
            int cnt = min(16, re - base);
            int t = 0;
            for (; t + 4 <= cnt; t += 4) {
                uint4 u[4]; float w[4];
#pragma unroll
                for (int q = 0; q < 4; q++) {
                    int ss = __shfl_sync(hmask, ew.x, (h << 4) + t + q);
                    int wb = __shfl_sync(hmask, ew.y, (h << 4) + t + q);
                    w[q] = __int_as_float(wb) * din;
                    u[q] = *(const uint4*)(g_h1h + (size_t)ss * HID + hl * 8);
                }
#pragma unroll
                for (int q = 0; q < 4; q++) {
                    const __half2* vp = (const __half2*)&u[q];
                    float2 a = __half22float2(vp[0]), b = __half22float2(vp[1]);
                    float2 c = __half22float2(vp[2]), d = __half22float2(vp[3]);
                    acc0.x = fmaf(w[q], a.x, acc0.x); acc0.y = fmaf(w[q], a.y, acc0.y);
                    acc0.z = fmaf(w[q], b.x, acc0.z); acc0.w = fmaf(w[q], b.y, acc0.w);
                    acc1.x = fmaf(w[q], c.x, acc1.x); acc1.y = fmaf(w[q], c.y, acc1.y);
                    acc1.z = fmaf(w[q], d.x, acc1.z); acc1.w = fmaf(w[q], d.y, acc1.w);
                }
            }
            for (; t < cnt; t++) {
                int ss = __shfl_sync(hmask, ew.x, (h << 4) + t);
                int wb = __shfl_sync(hmask, ew.y, (h << 4) + t);
                float w = __int_as_float(wb) * din;
                uint4 u = *(const uint4*)(g_h1h + (size_t)ss * HID + hl * 8);
                const __half2* vp = (const __half2*)&u;
                float2 a = __half22float2(vp[0]), b = __half22float2(vp[1]);
                float2 c = __half22float2(vp[2]), d = __half22float2(vp[3]);
                acc0.x = fmaf(w, a.x, acc0.x); acc0.y = fmaf(w, a.y, acc0.y);
                acc0.z = fmaf(w, b.x, acc0.z); acc0.w = fmaf(w, b.y, acc0.w);
                acc1.x = fmaf(w, c.x, acc1.x); acc1.y = fmaf(w, c.y, acc1.y);
                acc1.z = fmaf(w, d.x, acc1.z); acc1.w = fmaf(w, d.y, acc1.w);
            }
        }

        acc0.x = fmaxf(acc0.x, 0.f); acc0.y = fmaxf(acc0.y, 0.f);
        acc0.z = fmaxf(acc0.z, 0.f); acc0.w = fmaxf(acc0.w, 0.f);
        acc1.x = fmaxf(acc1.x, 0.f); acc1.y = fmaxf(acc1.y, 0.f);
        acc1.z = fmaxf(acc1.z, 0.f); acc1.w = fmaxf(acc1.w, 0.f);
        *(float4*)&s_agg[wid * 2 + h][hl * 8] = acc0;
        *(float4*)&s_agg[wid * 2 + h][hl * 8 + 4] = acc1;
    }
    __syncwarp();

    // GEMM2 epilogue: two 18-lane passes over the warp's 2 nodes
#pragma unroll
    for (int nn = 0; nn < 2; nn++) {
        int nd = blockIdx.x * 16 + wid * 2 + nn;
        if (lane < OUTC && nd < NNODES) {
            float p = 0.f;
#pragma unroll
            for (int k = 0; k < HID; k += 4) {
                const float4 a = *(const float4*)&s_agg[wid * 2 + nn][k];
                const float4 w = *(const float4*)&W2t[lane * W2S + k];
                p += a.x * w.x + a.y * w.y + a.z * w.z + a.w * w.w;
            }
            g_h2h[(size_t)nd * OUTC + lane] = __float2half_rn(p);
        }
    }
}

// ---------------- Layer 2: half2 gathers (9 lanes), log_softmax ----------------
__global__ __launch_bounds__(256) void k_layer2(const float* __restrict__ b2,
                                                float* __restrict__ out) {
    int node = (blockIdx.x * blockDim.x + threadIdx.x) >> 5;
    int lane = threadIdx.x & 31;
    if (node >= NNODES) return;

    float din = g_dinv[node];
    int rs = g_rowstart[node];
    int re = g_rowstart[node + 1];

    float2 acc = make_float2(0.f, 0.f);
    if (lane < 9) {
        __half2 hv = *(const __half2*)(g_h2h + (size_t)node * OUTC + 2 * lane);
        float2 f = __half22float2(hv);
        float di2 = din * din;
        acc.x = b2[2 * lane]     + di2 * f.x;
        acc.y = b2[2 * lane + 1] + di2 * f.y;
    }

    for (int base = rs; base < re; base += 32) {
        int j = base + lane;
        int2 ew = (j < re) ? g_cadj[j] : make_int2(0, 0);
        int cnt = min(32, re - base);
        int t = 0;
        for (; t + 4 <= cnt; t += 4) {
            float2 v[4]; float w[4];
#pragma unroll
            for (int q = 0; q < 4; q++) {
                int ss = __shfl_sync(0xffffffffu, ew.x, t + q);
                int wb = __shfl_sync(0xffffffffu, ew.y, t + q);
                w[q] = __int_as_float(wb) * din;
                v[q] = make_float2(0.f, 0.f);
                if (lane < 9)
                    v[q] = __half22float2(*(const __half2*)(g_h2h + (size_t)ss * OUTC + 2 * lane));
            }
#pragma unroll
            for (int q = 0; q < 4; q++) {
                acc.x = fmaf(w[q], v[q].x, acc.x);
                acc.y = fmaf(w[q], v[q].y, acc.y);
            }
        }
        for (; t < cnt; t++) {
            int ss = __shfl_sync(0xffffffffu, ew.x, t);
            int wb = __shfl_sync(0xffffffffu, ew.y, t);
            float w = __int_as_float(wb) * din;
            if (lane < 9) {
                float2 v = __half22float2(*(const __half2*)(g_h2h + (size_t)ss * OUTC + 2 * lane));
                acc.x = fmaf(w, v.x, acc.x);
                acc.y = fmaf(w, v.y, acc.y);
            }
        }
    }

    // log_softmax across 9 lanes x 2 values
    float m = (lane < 9) ? fmaxf(acc.x, acc.y) : -1e30f;
#pragma unroll
    for (int off = 16; off; off >>= 1)
        m = fmaxf(m, __shfl_xor_sync(0xffffffffu, m, off));
    float e = (lane < 9) ? (expf(acc.x - m) + expf(acc.y - m)) : 0.f;
#pragma unroll
    for (int off = 16; off; off >>= 1)
        e += __shfl_xor_sync(0xffffffffu, e, off);
    float ls = m + logf(e);
    if (lane < 9) {
        float2 o = make_float2(acc.x - ls, acc.y - ls);
        *(float2*)(out + (size_t)node * OUTC + 2 * lane) = o;
    }
}

// ---------------- launch ----------------
extern "C" void kernel_launch(void* const* d_in, const int* in_sizes, int n_in,
                              void* d_out, int out_size) {
    const float* x = 0; const void* ei = 0;
    const float* W1 = 0; const float* b1 = 0;
    const float* W2 = 0; const float* b2 = 0;
    for (int i = 0; i < n_in; i++) {
        long long sz = in_sizes[i];
        if (sz == (long long)NNODES * INC) x = (const float*)d_in[i];
        else if (sz == 2LL * NEDGES)       ei = d_in[i];
        else if (sz == (long long)INC * HID) W1 = (const float*)d_in[i];
        else if (sz == HID)                b1 = (const float*)d_in[i];
        else if (sz == (long long)HID * OUTC) W2 = (const float*)d_in[i];
        else if (sz == OUTC)               b2 = (const float*)d_in[i];
    }
    float* out = (float*)d_out;

    cudaFuncSetAttribute(k_gemm1_mma, cudaFuncAttributeMaxDynamicSharedMemorySize, GEMM1_SMEM);

    k_prep<<<(NNODES * INC / 4 + 255) / 256, 256>>>((const unsigned int*)ei, x, W1); // 1
    k_count<<<(NEDGES + 255) / 256, 256>>>(ei);                                      // 2
    k_scan1<<<NB, 1024>>>();                                                         // 3
    k_gemm1_mma<<<(NNODES + 127) / 128, 256, GEMM1_SMEM>>>();                        // 4 (profiled)
    k_scan3f<<<(NNODES + 255) / 256, 256>>>();                                       // 5
    k_fill<<<(NEDGES + 255) / 256, 256>>>(ei);                                       // 6
    {
        long long thr = (long long)NNODES * 16;  // 2 nodes per warp
        k_layer1<<<(unsigned)((thr + 255) / 256), 256>>>(b1, W2);                    // 7
    }
    {
        long long thr = (long long)NNODES * 32;
        k_layer2<<<(unsigned)((thr + 255) / 256), 256>>>(b2, out);                   // 8
    }
}

// round 9
// speedup vs baseline: 2.4796x; 1.0431x over previous
#include <cuda_runtime.h>
#include <cuda_fp16.h>
#include <math.h>

#define NNODES 100000
#define NEDGES 1600000
#define INC 128
#define HID 128
#define OUTC 18
#define NB 98   // ceil(NNODES/1024)
#define W2S 132 // padded W2t row stride (floats)

// ---------------- scratch ----------------
__device__ __align__(16) float g_dinv[NNODES];
__device__ __align__(16) __half g_xh[(size_t)NNODES * INC];
__device__ __align__(16) __half g_w1h[INC * HID];
__device__ __align__(16) __half g_h1h[(size_t)NNODES * HID];
__device__ __align__(16) __half g_h2h[(size_t)NNODES * OUTC];
__device__ int g_degi[NNODES];          // zero at start of each run (static init / reset by scan3f)
__device__ int g_rowstart[NNODES + 1];
__device__ int g_cursor[NNODES];
__device__ __align__(8) int2 g_cadj[NEDGES];   // {src, dinv[src] bits}
__device__ int g_bsum[128];
__device__ int g_is64;

// ---------------- K1: detect + degree count + fp16 convert (fused) ----------------
__global__ void k_prep(const void* __restrict__ ei,
                       const float* __restrict__ x, const float* __restrict__ W1) {
    __shared__ int s_is64;
    const unsigned int* eiw = (const unsigned int*)ei;
    if (threadIdx.x < 32) {
        unsigned int any = 0;
        for (int q = threadIdx.x; q < 128; q += 32) any |= eiw[2 * q + 1];
        unsigned int b = __ballot_sync(0xffffffffu, any != 0u);
        if (threadIdx.x == 0) s_is64 = (b == 0u);
    }
    __syncthreads();
    int i = blockIdx.x * blockDim.x + threadIdx.x;
    if (i == 0) g_is64 = s_is64;
    if (i < NEDGES) {
        int d = s_is64 ? (int)((const long long*)ei)[NEDGES + i]
                       : ((const int*)ei)[NEDGES + i];
        atomicAdd(&g_degi[d], 1);
    }
    if (i < NNODES * INC / 4) {
        float4 v = ((const float4*)x)[i];
        __half2 lo = __floats2half2_rn(v.x, v.y);
        __half2 hi = __floats2half2_rn(v.z, v.w);
        uint2 u;
        u.x = *(unsigned int*)&lo;
        u.y = *(unsigned int*)&hi;
        *(uint2*)(g_xh + (size_t)i * 4) = u;
    }
    if (i < INC * HID / 4) {
        float4 v = ((const float4*)W1)[i];
        __half2 lo = __floats2half2_rn(v.x, v.y);
        __half2 hi = __floats2half2_rn(v.z, v.w);
        uint2 u;
        u.x = *(unsigned int*)&lo;
        u.y = *(unsigned int*)&hi;
        *(uint2*)(g_w1h + (size_t)i * 4) = u;
    }
}

// ---------------- scan phase 1 ----------------
__global__ __launch_bounds__(1024) void k_scan1() {
    __shared__ int sh[1024];
    int i = blockIdx.x * 1024 + threadIdx.x;
    int v = (i < NNODES) ? g_degi[i] : 0;
    sh[threadIdx.x] = v;
    __syncthreads();
    for (int off = 1; off < 1024; off <<= 1) {
        int t = (threadIdx.x >= off) ? sh[threadIdx.x - off] : 0;
        __syncthreads();
        sh[threadIdx.x] += t;
        __syncthreads();
    }
    if (i < NNODES) g_rowstart[i] = sh[threadIdx.x] - v;
    if (threadIdx.x == 1023) g_bsum[blockIdx.x] = sh[1023];
}

// ---------------- scan phases 2+3 fused; also resets degi for next run ----------------
__global__ __launch_bounds__(256) void k_scan3f() {
    __shared__ int sh[128];
    int t = threadIdx.x;
    int v0 = 0;
    if (t < 128) {
        v0 = (t < NB) ? g_bsum[t] : 0;
        sh[t] = v0;
    }
    __syncthreads();
    for (int off = 1; off < 128; off <<= 1) {
        int u = (t < 128 && t >= off) ? sh[t - off] : 0;
        __syncthreads();
        if (t < 128) sh[t] += u;
        __syncthreads();
    }
    if (t < 128) {
        int ex = sh[t] - v0;
        __syncthreads();
        sh[t] = ex;
    }
    __syncthreads();
    int i = blockIdx.x * 256 + t;
    if (i < NNODES) {
        int r = g_rowstart[i] + sh[i >> 10];
        g_rowstart[i] = r;
        g_cursor[i] = r;
        g_dinv[i] = rsqrtf(1.0f + (float)g_degi[i]);
        g_degi[i] = 0;   // reset for next run (deterministic steady state)
    }
    if (i == 0) g_rowstart[NNODES] = NEDGES;
}

// ---------------- CSR fill (launch #4 — profiled) ----------------
__global__ void k_fill(const void* __restrict__ ei) {
    int e = blockIdx.x * blockDim.x + threadIdx.x;
    if (e >= NEDGES) return;
    int s, d;
    if (g_is64) {
        const long long* p = (const long long*)ei;
        s = (int)p[e];
        d = (int)p[NEDGES + e];
    } else {
        const int* p = (const int*)ei;
        s = p[e];
        d = p[NEDGES + e];
    }
    int pos = atomicAdd(&g_cursor[d], 1);
    g_cadj[pos] = make_int2(s, __float_as_int(g_dinv[s]));
}

// ---------------- K: GEMM1 tensor cores, 512 thr, cp.async double buffer ----------------
#define XS_STRIDE 144
#define WS_STRIDE 272
#define SX_BYTES (128 * XS_STRIDE)
#define SW_BYTES (64 * WS_STRIDE)
#define PHASE_BYTES (SX_BYTES + SW_BYTES)
#define GEMM1_SMEM (2 * PHASE_BYTES)

__device__ __forceinline__ void cp16(unsigned int dst, const void* src, int srcsize) {
    asm volatile("cp.async.cg.shared.global [%0], [%1], 16, %2;"
                 :: "r"(dst), "l"(src), "r"(srcsize));
}

__global__ __launch_bounds__(512, 2) void k_gemm1_mma() {
    extern __shared__ __align__(16) unsigned char dynsmem[];
    const int tid = threadIdx.x;
    const int wid = tid >> 5;        // 0..15
    const int lane = tid & 31;
    const int slab = wid >> 1;       // 0..7 -> rows [16*slab, +16)
    const int half = wid & 1;        // 0..1 -> cols [64*half, +64)
    const int row0 = blockIdx.x * 128;

#pragma unroll
    for (int kp = 0; kp < 2; kp++) {
        unsigned char* s_x = dynsmem + kp * PHASE_BYTES;
        unsigned char* s_w = s_x + SX_BYTES;
        for (int i = tid; i < 128 * 8; i += 512) {
            int r = i >> 3, c = i & 7;
            const void* src = g_xh + (size_t)(row0 + r) * INC + kp * 64 + c * 8;
            int vsz = (row0 + r < NNODES) ? 16 : 0;
            unsigned int dst = (unsigned int)__cvta_generic_to_shared(s_x + r * XS_STRIDE + c * 16);
            cp16(dst, src, vsz);
        }
        for (int i = tid; i < 64 * 16; i += 512) {
            int r = i >> 4, c = i & 15;
            const void* src = g_w1h + (size_t)(kp * 64 + r) * HID + c * 8;
            unsigned int dst = (unsigned int)__cvta_generic_to_shared(s_w + r * WS_STRIDE + c * 16);
            cp16(dst, src, 16);
        }
        asm volatile("cp.async.commit_group;");
    }

    float acc[8][4];
#pragma unroll
    for (int t = 0; t < 8; t++)
#pragma unroll
        for (int q = 0; q < 4; q++) acc[t][q] = 0.0f;

#pragma unroll
    for (int kp = 0; kp < 2; kp++) {
        if (kp == 0) asm volatile("cp.async.wait_group 1;");
        else         asm volatile("cp.async.wait_group 0;");
        __syncthreads();
        unsigned char* s_x = dynsmem + kp * PHASE_BYTES;
        unsigned char* s_w = s_x + SX_BYTES;

#pragma unroll
        for (int kk = 0; kk < 4; kk++) {
            unsigned int a0, a1, a2, a3;
            {
                const unsigned char* p = s_x + (slab * 16 + (lane & 15)) * XS_STRIDE
                                             + kk * 32 + (lane >> 4) * 16;
                unsigned int sa = (unsigned int)__cvta_generic_to_shared(p);
                asm volatile("ldmatrix.sync.aligned.m8n8.x4.shared.b16 {%0,%1,%2,%3}, [%4];"
                             : "=r"(a0), "=r"(a1), "=r"(a2), "=r"(a3) : "r"(sa));
            }
#pragma unroll
            for (int j = 0; j < 4; j++) {
                unsigned int b0, b1, b2, b3;
                const unsigned char* p = s_w + (kk * 16 + (lane & 15)) * WS_STRIDE
                                             + half * 128 + j * 32 + (lane >> 4) * 16;
                unsigned int sb = (unsigned int)__cvta_generic_to_shared(p);
                asm volatile("ldmatrix.sync.aligned.m8n8.x4.trans.shared.b16 {%0,%1,%2,%3}, [%4];"
                             : "=r"(b0), "=r"(b1), "=r"(b2), "=r"(b3) : "r"(sb));
                asm volatile("mma.sync.aligned.m16n8k16.row.col.f32.f16.f16.f32 "
                             "{%0,%1,%2,%3}, {%4,%5,%6,%7}, {%8,%9}, {%0,%1,%2,%3};"
                             : "+f"(acc[2 * j][0]), "+f"(acc[2 * j][1]),
                               "+f"(acc[2 * j][2]), "+f"(acc[2 * j][3])
                             : "r"(a0), "r"(a1), "r"(a2), "r"(a3), "r"(b0), "r"(b1));
                asm volatile("mma.sync.aligned.m16n8k16.row.col.f32.f16.f16.f32 "
                             "{%0,%1,%2,%3}, {%4,%5,%6,%7}, {%8,%9}, {%0,%1,%2,%3};"
                             : "+f"(acc[2 * j + 1][0]), "+f"(acc[2 * j + 1][1]),
                               "+f"(acc[2 * j + 1][2]), "+f"(acc[2 * j + 1][3])
                             : "r"(a0), "r"(a1), "r"(a2), "r"(a3), "r"(b2), "r"(b3));
            }
        }
        __syncthreads();
    }

    int gr = lane >> 2;
    int gc = (lane & 3) * 2;
    int r1 = row0 + slab * 16 + gr;
    int r2 = r1 + 8;
#pragma unroll
    for (int t = 0; t < 8; t++) {
        int col = half * 64 + t * 8 + gc;
        if (r1 < NNODES) {
            __half2 h = __floats2half2_rn(acc[t][0], acc[t][1]);
            *(__half2*)(g_h1h + (size_t)r1 * HID + col) = h;
        }
        if (r2 < NNODES) {
            __half2 h = __floats2half2_rn(acc[t][2], acc[t][3]);
            *(__half2*)(g_h1h + (size_t)r2 * HID + col) = h;
        }
    }
}

// ---------------- Layer 1: 2 nodes/warp, 16 lanes/node, unroll 8 ----------------
__global__ __launch_bounds__(256) void k_layer1(const float* __restrict__ b1,
                                                const float* __restrict__ W2) {
    __shared__ float W2t[OUTC * W2S];
    __shared__ float s_agg[16][HID];
    for (int i = threadIdx.x; i < HID * OUTC; i += blockDim.x) {
        int k = i / OUTC, oc = i % OUTC;
        W2t[oc * W2S + k] = W2[i];
    }
    __syncthreads();

    const int wid = threadIdx.x >> 5;
    const int lane = threadIdx.x & 31;
    const int h = lane >> 4;
    const int hl = lane & 15;
    const unsigned hmask = h ? 0xffff0000u : 0x0000ffffu;
    const int node = blockIdx.x * 16 + wid * 2 + h;

    if (node < NNODES) {
        float din = g_dinv[node];
        int rs = g_rowstart[node];
        int re = g_rowstart[node + 1];

        uint4 us = *(const uint4*)(g_h1h + (size_t)node * HID + hl * 8);
        const __half2* up = (const __half2*)&us;
        float2 f0 = __half22float2(up[0]), f1 = __half22float2(up[1]);
        float2 f2 = __half22float2(up[2]), f3 = __half22float2(up[3]);
        float di2 = din * din;
        float4 ba = *(const float4*)(b1 + hl * 8);
        float4 bb = *(const float4*)(b1 + hl * 8 + 4);
        float4 acc0, acc1;
        acc0.x = ba.x + di2 * f0.x; acc0.y = ba.y + di2 * f0.y;
        acc0.z = ba.z + di2 * f1.x; acc0.w = ba.w + di2 * f1.y;
        acc1.x = bb.x + di2 * f2.x; acc1.y = bb.y + di2 * f2.y;
        acc1.z = bb.z + di2 * f3.x; acc1.w = bb.w + di2 * f3.y;

        for (int base = rs; base < re; base += 16) {
            int j = base + hl;
            int2 ew = (j < re) ? g_cadj[j] : make_int2(0, 0);
            int cnt = min(16, re - base);
            int t = 0;
            for (; t + 8 <= cnt; t += 8) {
                uint4 u[8]; float w[8];
#pragma unroll
                for (int q = 0; q < 8; q++) {
                    int ss = __shfl_sync(hmask, ew.x, (h << 4) + t + q);
                    int wb = __shfl_sync(hmask, ew.y, (h << 4) + t + q);
                    w[q] = __int_as_float(wb) * din;
                    u[q] = *(const uint4*)(g_h1h + (size_t)ss * HID + hl * 8);
                }
#pragma unroll
                for (int q = 0; q < 8; q++) {
                    const __half2* vp = (const __half2*)&u[q];
                    float2 a = __half22float2(vp[0]), b = __half22float2(vp[1]);
                    float2 c = __half22float2(vp[2]), d = __half22float2(vp[3]);
                    acc0.x = fmaf(w[q], a.x, acc0.x); acc0.y = fmaf(w[q], a.y, acc0.y);
                    acc0.z = fmaf(w[q], b.x, acc0.z); acc0.w = fmaf(w[q], b.y, acc0.w);
                    acc1.x = fmaf(w[q], c.x, acc1.x); acc1.y = fmaf(w[q], c.y, acc1.y);
                    acc1.z = fmaf(w[q], d.x, acc1.z); acc1.w = fmaf(w[q], d.y, acc1.w);
                }
            }
            for (; t < cnt; t++) {
                int ss = __shfl_sync(hmask, ew.x, (h << 4) + t);
                int wb = __shfl_sync(hmask, ew.y, (h << 4) + t);
                float w = __int_as_float(wb) * din;
                uint4 u = *(const uint4*)(g_h1h + (size_t)ss * HID + hl * 8);
                const __half2* vp = (const __half2*)&u;
                float2 a = __half22float2(vp[0]), b = __half22float2(vp[1]);
                float2 c = __half22float2(vp[2]), d = __half22float2(vp[3]);
                acc0.x = fmaf(w, a.x, acc0.x); acc0.y = fmaf(w, a.y, acc0.y);
                acc0.z = fmaf(w, b.x, acc0.z); acc0.w = fmaf(w, b.y, acc0.w);
                acc1.x = fmaf(w, c.x, acc1.x); acc1.y = fmaf(w, c.y, acc1.y);
                acc1.z = fmaf(w, d.x, acc1.z); acc1.w = fmaf(w, d.y, acc1.w);
            }
        }

        acc0.x = fmaxf(acc0.x, 0.f); acc0.y = fmaxf(acc0.y, 0.f);
        acc0.z = fmaxf(acc0.z, 0.f); acc0.w = fmaxf(acc0.w, 0.f);
        acc1.x = fmaxf(acc1.x, 0.f); acc1.y = fmaxf(acc1.y, 0.f);
        acc1.z = fmaxf(acc1.z, 0.f); acc1.w = fmaxf(acc1.w, 0.f);
        *(float4*)&s_agg[wid * 2 + h][hl * 8] = acc0;
        *(float4*)&s_agg[wid * 2 + h][hl * 8 + 4] = acc1;
    }
    __syncwarp();

#pragma unroll
    for (int nn = 0; nn < 2; nn++) {
        int nd = blockIdx.x * 16 + wid * 2 + nn;
        if (lane < OUTC && nd < NNODES) {
            float p = 0.f;
#pragma unroll
            for (int k = 0; k < HID; k += 4) {
                const float4 a = *(const float4*)&s_agg[wid * 2 + nn][k];
                const float4 w = *(const float4*)&W2t[lane * W2S + k];
                p += a.x * w.x + a.y * w.y + a.z * w.z + a.w * w.w;
            }
            g_h2h[(size_t)nd * OUTC + lane] = __float2half_rn(p);
        }
    }
}

// ---------------- Layer 2: 2 nodes/warp, half2 gathers, log_softmax ----------------
__global__ __launch_bounds__(256) void k_layer2(const float* __restrict__ b2,
                                                float* __restrict__ out) {
    const int wid = threadIdx.x >> 5;
    const int lane = threadIdx.x & 31;
    const int h = lane >> 4;
    const int hl = lane & 15;
    const unsigned hmask = h ? 0xffff0000u : 0x0000ffffu;
    const int node = blockIdx.x * 16 + wid * 2 + h;
    if (node >= NNODES) return;

    float din = g_dinv[node];
    int rs = g_rowstart[node];
    int re = g_rowstart[node + 1];

    float2 acc = make_float2(0.f, 0.f);
    if (hl < 9) {
        __half2 hv = *(const __half2*)(g_h2h + (size_t)node * OUTC + 2 * hl);
        float2 f = __half22float2(hv);
        float di2 = din * din;
        acc.x = b2[2 * hl]     + di2 * f.x;
        acc.y = b2[2 * hl + 1] + di2 * f.y;
    }

    for (int base = rs; base < re; base += 16) {
        int j = base + hl;
        int2 ew = (j < re) ? g_cadj[j] : make_int2(0, 0);
        int cnt = min(16, re - base);
        int t = 0;
        for (; t + 4 <= cnt; t += 4) {
            float2 v[4]; float w[4];
#pragma unroll
            for (int q = 0; q < 4; q++) {
                int ss = __shfl_sync(hmask, ew.x, (h << 4) + t + q);
                int wb = __shfl_sync(hmask, ew.y, (h << 4) + t + q);
                w[q] = __int_as_float(wb) * din;
                v[q] = make_float2(0.f, 0.f);
                if (hl < 9)
                    v[q] = __half22float2(*(const __half2*)(g_h2h + (size_t)ss * OUTC + 2 * hl));
            }
#pragma unroll
            for (int q = 0; q < 4; q++) {
                acc.x = fmaf(w[q], v[q].x, acc.x);
                acc.y = fmaf(w[q], v[q].y, acc.y);
            }
        }
        for (; t < cnt; t++) {
            int ss = __shfl_sync(hmask, ew.x, (h << 4) + t);
            int wb = __shfl_sync(hmask, ew.y, (h << 4) + t);
            float w = __int_as_float(wb) * din;
            if (hl < 9) {
                float2 v = __half22float2(*(const __half2*)(g_h2h + (size_t)ss * OUTC + 2 * hl));
                acc.x = fmaf(w, v.x, acc.x);
                acc.y = fmaf(w, v.y, acc.y);
            }
        }
    }

    // log_softmax within the 16-lane half (9 active lanes x 2 values)
    float m = (hl < 9) ? fmaxf(acc.x, acc.y) : -1e30f;
#pragma unroll
    for (int off = 8; off; off >>= 1)
        m = fmaxf(m, __shfl_xor_sync(hmask, m, off));
    float e = (hl < 9) ? (expf(acc.x - m) + expf(acc.y - m)) : 0.f;
#pragma unroll
    for (int off = 8; off; off >>= 1)
        e += __shfl_xor_sync(hmask, e, off);
    float ls = m + logf(e);
    if (hl < 9) {
        float2 o = make_float2(acc.x - ls, acc.y - ls);
        *(float2*)(out + (size_t)node * OUTC + 2 * hl) = o;
    }
}

// ---------------- launch ----------------
extern "C" void kernel_launch(void* const* d_in, const int* in_sizes, int n_in,
                              void* d_out, int out_size) {
    const float* x = 0; const void* ei = 0;
    const float* W1 = 0; const float* b1 = 0;
    const float* W2 = 0; const float* b2 = 0;
    for (int i = 0; i < n_in; i++) {
        long long sz = in_sizes[i];
        if (sz == (long long)NNODES * INC) x = (const float*)d_in[i];
        else if (sz == 2LL * NEDGES)       ei = d_in[i];
        else if (sz == (long long)INC * HID) W1 = (const float*)d_in[i];
        else if (sz == HID)                b1 = (const float*)d_in[i];
        else if (sz == (long long)HID * OUTC) W2 = (const float*)d_in[i];
        else if (sz == OUTC)               b2 = (const float*)d_in[i];
    }
    float* out = (float*)d_out;

    cudaFuncSetAttribute(k_gemm1_mma, cudaFuncAttributeMaxDynamicSharedMemorySize, GEMM1_SMEM);

    k_prep<<<(NNODES * INC / 4 + 255) / 256, 256>>>(ei, x, W1);                      // 1
    k_scan1<<<NB, 1024>>>();                                                         // 2
    k_scan3f<<<(NNODES + 255) / 256, 256>>>();                                       // 3
    k_fill<<<(NEDGES + 255) / 256, 256>>>(ei);                                       // 4 (profiled)
    k_gemm1_mma<<<(NNODES + 127) / 128, 512, GEMM1_SMEM>>>();                        // 5
    {
        long long thr = (long long)NNODES * 16;
        k_layer1<<<(unsigned)((thr + 255) / 256), 256>>>(b1, W2);                    // 6
        k_layer2<<<(unsigned)((thr + 255) / 256), 256>>>(b2, out);                   // 7
    }
}